// round 11
// baseline (speedup 1.0000x reference)
#include <cuda_runtime.h>
#include <cuda_bf16.h>
#include <cstdint>

#define Bb 2
#define Tt 2048
#define Cc 1024
#define Hh 16
#define HD 64

typedef unsigned long long ull;
typedef unsigned int uint32;

// Packed f32x2 helpers (sm_103a): only reachable via PTX fma.rn.f32x2.
#define FMA2(d, a, b) \
    asm("fma.rn.f32x2 %0, %1, %2, %0;" : "+l"(d) : "l"(a), "l"(b))
#define MUL2_IP(d, a) \
    asm("mul.rn.f32x2 %0, %1, %0;" : "+l"(d) : "l"(a))

__device__ __forceinline__ ull pack2(float lo, float hi) {
    ull r;
    asm("mov.b64 %0, {%1, %2};" : "=l"(r) : "f"(lo), "f"(hi));
    return r;
}
__device__ __forceinline__ void unpack2(ull v, float& lo, float& hi) {
    asm("mov.b64 {%0, %1}, %2;" : "=f"(lo), "=f"(hi) : "l"(v));
}
__device__ __forceinline__ void cpasync16(uint32 dst, const void* src) {
    asm volatile("cp.async.cg.shared.global [%0], [%1], 16;" :: "r"(dst), "l"(src) : "memory");
}
__device__ __forceinline__ void cpasync_commit() {
    asm volatile("cp.async.commit_group;" ::: "memory");
}
__device__ __forceinline__ void cpasync_wait0() {
    asm volatile("cp.async.wait_group 0;" ::: "memory");
}

// Scratch (allocation-free rule: __device__ globals)
__device__ float g_q3[(size_t)Bb*Hh*Tt*3];           // (b,h,t,3)
__device__ float g_ka[(size_t)Bb*Hh*Tt*3];           // (b,h,t,3) transformed keys
__device__ float g_v [(size_t)Bb*Hh*Tt*HD];          // (b,h,t,64)
__device__ float g_ao[(size_t)Bb*Tt*Cc];             // (b,t,c) attention output

// Skew helper for duplicated-A smem: +4 floats per 32-float (128B) group.
#define APOS(c) ((c) + (((c) >> 5) << 2))

// ---------------------------------------------------------------------------
// Kernel 1: QK projection + fold (scale*I + d d^T) into K.
// ---------------------------------------------------------------------------
__global__ void proj_qk_kernel(const float* __restrict__ x,
                               const float* __restrict__ wq,
                               const float* __restrict__ wk,
                               const float* __restrict__ dirs,
                               const float* __restrict__ scale_p) {
    __shared__ float xs[8][Cc];
    __shared__ float sk[8][48];
    const int tid = threadIdx.x;                 // 128
    const int rowBase = blockIdx.x * 8;

    {
        const float4* src = (const float4*)(x + (size_t)rowBase * Cc);
        float4* dst = (float4*)&xs[0][0];
        #pragma unroll
        for (int i = tid; i < 8 * Cc / 4; i += 128) dst[i] = src[i];
    }
    __syncthreads();

    if (tid < 96) {
        const int col = tid % 48;
        const float* __restrict__ w = (tid < 48) ? wq : wk;
        float acc[8];
        #pragma unroll
        for (int r = 0; r < 8; r++) acc[r] = 0.f;
        for (int i = 0; i < Cc; i += 4) {
            float w0 = w[(i + 0) * 48 + col];
            float w1 = w[(i + 1) * 48 + col];
            float w2 = w[(i + 2) * 48 + col];
            float w3 = w[(i + 3) * 48 + col];
            #pragma unroll
            for (int r = 0; r < 8; r++) {
                float4 xv = *(const float4*)&xs[r][i];
                acc[r] = fmaf(xv.x, w0, fmaf(xv.y, w1, fmaf(xv.z, w2, fmaf(xv.w, w3, acc[r]))));
            }
        }
        const int h = col / 3, d = col % 3;
        if (tid < 48) {
            #pragma unroll
            for (int r = 0; r < 8; r++) {
                int row = rowBase + r;
                int b = row / Tt, t = row % Tt;
                g_q3[(((size_t)b * Hh + h) * Tt + t) * 3 + d] = acc[r];
            }
        } else {
            #pragma unroll
            for (int r = 0; r < 8; r++) sk[r][col] = acc[r];
        }
    }
    __syncthreads();

    {
        const int r = tid >> 4, h = tid & 15;
        const float d0 = dirs[h * 3 + 0], d1 = dirs[h * 3 + 1], d2 = dirs[h * 3 + 2];
        const float sc = scale_p[0];
        const float k0 = sk[r][3 * h + 0], k1 = sk[r][3 * h + 1], k2 = sk[r][3 * h + 2];
        const float dot = d0 * k0 + d1 * k1 + d2 * k2;
        int row = rowBase + r;
        int b = row / Tt, t = row % Tt;
        size_t base = (((size_t)b * Hh + h) * Tt + t) * 3;
        g_ka[base + 0] = sc * k0 + d0 * dot;
        g_ka[base + 1] = sc * k1 + d1 * dot;
        g_ka[base + 2] = sc * k2 + d2 * dot;
    }
}

// ---------------------------------------------------------------------------
// Kernel 2/4: fp32 GEMM with packed fma.rn.f32x2, double-buffered pipeline.
// 64x64 tile, BK=8, 64 threads, grid=1024.
// A stored DUPLICATED+skewed in smem ((a,a) pairs -> packed operand straight
// from LDS); B natural col-pairs. 6 LDS + 32 FMA2 per kk, zero pack movs.
// B prefetch: cp.async.cg; A prefetch: LDG->regs, STS after compute.
// ---------------------------------------------------------------------------
template <bool SCATTER>
__global__ void __launch_bounds__(64, 7)
gemm_kernel(const float* __restrict__ A,
            const float* __restrict__ Bw,
            float* __restrict__ Cout) {
    const int N = Cc;           // 1024
    const int K = Cc;           // 1024
    __shared__ float As[2][8][140];   // duplicated: APOS(2*row), APOS(2*row)+1
    __shared__ float Bs[2][8][72];    // natural, 16B pad per 128B

    const int tid = threadIdx.x;   // 64
    const int tx = tid & 7;
    const int ty = tid >> 3;
    const int rowBase = blockIdx.y * 64;
    const int colBase = blockIdx.x * 64;

    ull acc[8][4];
    #pragma unroll
    for (int i = 0; i < 8; i++)
        #pragma unroll
        for (int j = 0; j < 4; j++) acc[i][j] = 0ULL;

    const int bRow = tid >> 3;               // k within B tile
    const int bColL = (tid & 7) * 8;
    const int bPos = bColL + ((bColL >> 5) << 2);
    const int rb = bPos;                     // B read base (same skew rule)
    const int ra = APOS(ty * 16);            // A-dup read base (16 floats, one group)
    const int wa = APOS(2 * tid);            // A-dup write base

    const float* aSrc = A + (size_t)(rowBase + tid) * K;
    const float* bSrc = Bw + (size_t)bRow * N + colBase + bColL;

    uint32 bDst0 = (uint32)__cvta_generic_to_shared(&Bs[0][bRow][bPos]);
    uint32 bDst1 = (uint32)__cvta_generic_to_shared(&Bs[1][bRow][bPos]);

    // ---- prologue: fill buffer 0 ----
    {
        float4 a0 = *(const float4*)(aSrc + 0);
        float4 a1 = *(const float4*)(aSrc + 4);
        cpasync16(bDst0, bSrc);
        cpasync16(bDst0 + 16, bSrc + 4);
        cpasync_commit();
        *(float2*)&As[0][0][wa] = make_float2(a0.x, a0.x);
        *(float2*)&As[0][1][wa] = make_float2(a0.y, a0.y);
        *(float2*)&As[0][2][wa] = make_float2(a0.z, a0.z);
        *(float2*)&As[0][3][wa] = make_float2(a0.w, a0.w);
        *(float2*)&As[0][4][wa] = make_float2(a1.x, a1.x);
        *(float2*)&As[0][5][wa] = make_float2(a1.y, a1.y);
        *(float2*)&As[0][6][wa] = make_float2(a1.z, a1.z);
        *(float2*)&As[0][7][wa] = make_float2(a1.w, a1.w);
        cpasync_wait0();
    }
    __syncthreads();

    for (int k0 = 0; k0 < K; k0 += 8) {
        const int cur = (k0 >> 3) & 1;
        const int nxt = cur ^ 1;
        const bool has = (k0 + 8) < K;

        float4 n0, n1;
        if (has) {
            uint32 bDstN = nxt ? bDst1 : bDst0;
            cpasync16(bDstN, bSrc + (size_t)(k0 + 8) * N);
            cpasync16(bDstN + 16, bSrc + (size_t)(k0 + 8) * N + 4);
            cpasync_commit();
            n0 = *(const float4*)(aSrc + k0 + 8);
            n1 = *(const float4*)(aSrc + k0 + 12);
        }

        #pragma unroll
        for (int kk = 0; kk < 8; kk++) {
            // A: 8 duplicated row-broadcast pairs via 4 LDS.128
            ulonglong2 a0v = *(const ulonglong2*)&As[cur][kk][ra + 0];
            ulonglong2 a1v = *(const ulonglong2*)&As[cur][kk][ra + 4];
            ulonglong2 a2v = *(const ulonglong2*)&As[cur][kk][ra + 8];
            ulonglong2 a3v = *(const ulonglong2*)&As[cur][kk][ra + 12];
            ull ap[8] = {a0v.x, a0v.y, a1v.x, a1v.y, a2v.x, a2v.y, a3v.x, a3v.y};
            // B: 4 natural col-pairs via 2 LDS.128
            ulonglong2 b01 = *(const ulonglong2*)&Bs[cur][kk][rb + 0];
            ulonglong2 b23 = *(const ulonglong2*)&Bs[cur][kk][rb + 4];
            ull bd[4] = {b01.x, b01.y, b23.x, b23.y};
            #pragma unroll
            for (int i = 0; i < 8; i++)
                #pragma unroll
                for (int j = 0; j < 4; j++)
                    FMA2(acc[i][j], ap[i], bd[j]);
        }

        if (has) {
            *(float2*)&As[nxt][0][wa] = make_float2(n0.x, n0.x);
            *(float2*)&As[nxt][1][wa] = make_float2(n0.y, n0.y);
            *(float2*)&As[nxt][2][wa] = make_float2(n0.z, n0.z);
            *(float2*)&As[nxt][3][wa] = make_float2(n0.w, n0.w);
            *(float2*)&As[nxt][4][wa] = make_float2(n1.x, n1.x);
            *(float2*)&As[nxt][5][wa] = make_float2(n1.y, n1.y);
            *(float2*)&As[nxt][6][wa] = make_float2(n1.z, n1.z);
            *(float2*)&As[nxt][7][wa] = make_float2(n1.w, n1.w);
            cpasync_wait0();
            __syncthreads();
        }
    }

    #pragma unroll
    for (int i = 0; i < 8; i++) {
        int m = rowBase + ty * 8 + i;
        #pragma unroll
        for (int j = 0; j < 4; j++) {
            int n0c = colBase + tx * 8 + 2 * j;     // even col -> pair in one head
            if (SCATTER) {
                int h = n0c >> 6, d = n0c & (HD - 1);
                int bi = m >> 11, t = m & (Tt - 1);
                *(ull*)&g_v[(((size_t)bi * Hh + h) * Tt + t) * HD + d] = acc[i][j];
            } else {
                *(ull*)&Cout[(size_t)m * N + n0c] = acc[i][j];
            }
        }
    }
}

// ---------------------------------------------------------------------------
// Kernel 3: causal flash attention, d_qk=3 (bias folded into ka), d_v=64.
// 128 threads; each thread owns TWO queries (q, q+64) x one 32-float d-half:
// per key, 8 LDS.128 feed 32 FMA2 (both queries) -> FMA2-bound, not LSU-bound.
// Diagonal tile splits into two branch-free loops (both / only-second).
// ---------------------------------------------------------------------------
__global__ void __launch_bounds__(128)
attn_kernel() {
    __shared__ float4 skv[128];        // key tile (k0,k1,k2,pad)
    __shared__ float  sv[128][HD];     // value tile 32KB
    __shared__ float  red[4];

    const int tid  = threadIdx.x;      // 128
    const int qp   = tid >> 1;         // query-pair index: 0..63
    const int half = tid & 1;          // d-half owner
    const int bh   = blockIdx.y;
    const int qt   = gridDim.x - 1 - blockIdx.x;   // heavy tiles first
    const int qAi  = qt * 128 + qp;
    const int qBi  = qAi + 64;

    const float* qpa = g_q3 + ((size_t)bh * Tt + qAi) * 3;
    const float qa0 = qpa[0], qa1 = qpa[1], qa2 = qpa[2];
    const float* qpb = g_q3 + ((size_t)bh * Tt + qBi) * 3;
    const float qb0 = qpb[0], qb1 = qpb[1], qb2 = qpb[2];
    const float qnA = sqrtf(qa0 * qa0 + qa1 * qa1 + qa2 * qa2);
    const float qnB = sqrtf(qb0 * qb0 + qb1 * qb1 + qb2 * qb2);

    float mA = -1e30f, lA = 0.f, mB = -1e30f, lB = 0.f;
    ull accA[16], accB[16];
    #pragma unroll
    for (int d = 0; d < 16; d++) { accA[d] = 0ULL; accB[d] = 0ULL; }

    const int kmaxTile = qt * 128 + 127;
    const float* kb = g_ka + (size_t)bh * Tt * 3;
    const float* vb = g_v  + (size_t)bh * Tt * HD;

    for (int s0 = 0; s0 <= kmaxTile; s0 += 128) {
        // Key tile + per-tile max |k|
        {
            const float* kpr = kb + (size_t)(s0 + tid) * 3;
            float k0 = kpr[0], k1 = kpr[1], k2 = kpr[2];
            skv[tid] = make_float4(k0, k1, k2, 0.f);
            float nk = sqrtf(k0 * k0 + k1 * k1 + k2 * k2);
            #pragma unroll
            for (int o = 16; o; o >>= 1) nk = fmaxf(nk, __shfl_xor_sync(0xffffffffu, nk, o));
            if ((tid & 31) == 0) red[tid >> 5] = nk;
        }
        // Value tile: 2048 float4 / 128 threads
        {
            const float4* vsrc = (const float4*)(vb + (size_t)s0 * HD);
            float4* vdst = (float4*)&sv[0][0];
            #pragma unroll
            for (int i = 0; i < 16; i++) vdst[tid + i * 128] = vsrc[tid + i * 128];
        }
        __syncthreads();

        const int sendA = min(128, qAi - s0 + 1);   // >= 1 always
        const int sendB = min(128, qBi - s0 + 1);   // >= sendA
        const float kmx = fmaxf(fmaxf(red[0], red[1]), fmaxf(red[2], red[3]));

        // Rescale both queries to tile-bound max (Cauchy-Schwarz)
        {
            const float mnA = fmaxf(mA, qnA * kmx);
            const float cA = __expf(mA - mnA);
            mA = mnA; lA *= cA;
            const ull cpA = pack2(cA, cA);
            #pragma unroll
            for (int d = 0; d < 16; d++) MUL2_IP(accA[d], cpA);
            const float mnB = fmaxf(mB, qnB * kmx);
            const float cB = __expf(mB - mnB);
            mB = mnB; lB *= cB;
            const ull cpB = pack2(cB, cB);
            #pragma unroll
            for (int d = 0; d < 16; d++) MUL2_IP(accB[d], cpB);
        }

        // Loop 1: both queries attend (s < sendA)
        for (int s = 0; s < sendA; s++) {
            float4 kv = skv[s];
            float scA = fmaf(qa0, kv.x, fmaf(qa1, kv.y, qa2 * kv.z));
            float scB = fmaf(qb0, kv.x, fmaf(qb1, kv.y, qb2 * kv.z));
            float pA = __expf(scA - mA); lA += pA;
            float pB = __expf(scB - mB); lB += pB;
            const ull ppA = pack2(pA, pA);
            const ull ppB = pack2(pB, pB);
            const ulonglong2* vr = (const ulonglong2*)sv[s];
            #pragma unroll
            for (int j = 0; j < 8; j++) {
                ulonglong2 vv = vr[2 * j + half];
                FMA2(accA[2 * j + 0], ppA, vv.x);
                FMA2(accA[2 * j + 1], ppA, vv.y);
                FMA2(accB[2 * j + 0], ppB, vv.x);
                FMA2(accB[2 * j + 1], ppB, vv.y);
            }
        }
        // Loop 2: only second query (sendA <= s < sendB) — diagonal tile only
        for (int s = sendA; s < sendB; s++) {
            float4 kv = skv[s];
            float scB = fmaf(qb0, kv.x, fmaf(qb1, kv.y, qb2 * kv.z));
            float pB = __expf(scB - mB); lB += pB;
            const ull ppB = pack2(pB, pB);
            const ulonglong2* vr = (const ulonglong2*)sv[s];
            #pragma unroll
            for (int j = 0; j < 8; j++) {
                ulonglong2 vv = vr[2 * j + half];
                FMA2(accB[2 * j + 0], ppB, vv.x);
                FMA2(accB[2 * j + 1], ppB, vv.y);
            }
        }
        __syncthreads();
    }

    const int b = bh >> 4, h = bh & 15;
    {
        const float invA = 1.f / lA;
        const ull ipA = pack2(invA, invA);
        float4* opA = (float4*)(g_ao + ((size_t)(b * Tt + qAi)) * Cc + h * HD);
        #pragma unroll
        for (int j = 0; j < 8; j++) {
            ull u0 = accA[2 * j + 0], u1 = accA[2 * j + 1];
            MUL2_IP(u0, ipA); MUL2_IP(u1, ipA);
            float4 o;
            unpack2(u0, o.x, o.y);
            unpack2(u1, o.z, o.w);
            opA[2 * j + half] = o;
        }
        const float invB = 1.f / lB;
        const ull ipB = pack2(invB, invB);
        float4* opB = (float4*)(g_ao + ((size_t)(b * Tt + qBi)) * Cc + h * HD);
        #pragma unroll
        for (int j = 0; j < 8; j++) {
            ull u0 = accB[2 * j + 0], u1 = accB[2 * j + 1];
            MUL2_IP(u0, ipB); MUL2_IP(u1, ipB);
            float4 o;
            unpack2(u0, o.x, o.y);
            unpack2(u1, o.z, o.w);
            opB[2 * j + half] = o;
        }
    }
}

// ---------------------------------------------------------------------------
extern "C" void kernel_launch(void* const* d_in, const int* in_sizes, int n_in,
                              void* d_out, int out_size) {
    const float* x     = (const float*)d_in[0];
    const float* wq    = (const float*)d_in[1];
    const float* wk    = (const float*)d_in[2];
    const float* wv    = (const float*)d_in[3];
    const float* wo    = (const float*)d_in[4];
    const float* dirs  = (const float*)d_in[5];
    const float* scale = (const float*)d_in[6];
    float* out = (float*)d_out;

    void *p_ao = nullptr;
    cudaGetSymbolAddress(&p_ao, g_ao);

    // 1. QK projection + key transform
    proj_qk_kernel<<<(Bb * Tt) / 8, 128>>>(x, wq, wk, dirs, scale);

    // 2. V projection GEMM (scatter to (b,h,t,64))
    gemm_kernel<true><<<dim3(Cc / 64, (Bb * Tt) / 64), 64>>>(x, wv, nullptr);

    // 3. Flash attention
    attn_kernel<<<dim3(Tt / 128, Bb * Hh), 128>>>();

    // 4. Output projection GEMM
    gemm_kernel<false><<<dim3(Cc / 64, (Bb * Tt) / 64), 64>>>((const float*)p_ao, wo, out);
}

// round 12
// speedup vs baseline: 1.0709x; 1.0709x over previous
#include <cuda_runtime.h>
#include <cuda_bf16.h>
#include <cstdint>

#define Bb 2
#define Tt 2048
#define Cc 1024
#define Hh 16
#define HD 64

typedef unsigned long long ull;
typedef unsigned int uint32;

// Packed f32x2 helpers (sm_103a): only reachable via PTX *.f32x2.
#define FMA2(d, a, b) \
    asm("fma.rn.f32x2 %0, %1, %2, %0;" : "+l"(d) : "l"(a), "l"(b))
#define MUL2_IP(d, a) \
    asm("mul.rn.f32x2 %0, %1, %0;" : "+l"(d) : "l"(a))
#define FMA2_N(d, a, b, c) \
    asm("fma.rn.f32x2 %0, %1, %2, %3;" : "=l"(d) : "l"(a), "l"(b), "l"(c))
#define MUL2_N(d, a, b) \
    asm("mul.rn.f32x2 %0, %1, %2;" : "=l"(d) : "l"(a), "l"(b))
#define ADD2_IP(d, a) \
    asm("add.rn.f32x2 %0, %1, %0;" : "+l"(d) : "l"(a))

__device__ __forceinline__ ull pack2(float lo, float hi) {
    ull r;
    asm("mov.b64 %0, {%1, %2};" : "=l"(r) : "f"(lo), "f"(hi));
    return r;
}
__device__ __forceinline__ void unpack2(ull v, float& lo, float& hi) {
    asm("mov.b64 {%0, %1}, %2;" : "=f"(lo), "=f"(hi) : "l"(v));
}
__device__ __forceinline__ void cpasync16(uint32 dst, const void* src) {
    asm volatile("cp.async.cg.shared.global [%0], [%1], 16;" :: "r"(dst), "l"(src) : "memory");
}
__device__ __forceinline__ void cpasync_commit() {
    asm volatile("cp.async.commit_group;" ::: "memory");
}
__device__ __forceinline__ void cpasync_wait0() {
    asm volatile("cp.async.wait_group 0;" ::: "memory");
}

// Scratch (allocation-free rule: __device__ globals)
__device__ float g_q3[(size_t)Bb*Hh*Tt*3];           // (b,h,t,3)
__device__ float g_ka[(size_t)Bb*Hh*Tt*3];           // (b,h,t,3) transformed keys
__device__ float g_v [(size_t)Bb*Hh*Tt*HD];          // (b,h,t,64)
__device__ float g_ao[(size_t)Bb*Tt*Cc];             // (b,t,c) attention output

// ---------------------------------------------------------------------------
// Kernel 1: QK projection + fold (scale*I + d d^T) into K.
// ---------------------------------------------------------------------------
__global__ void proj_qk_kernel(const float* __restrict__ x,
                               const float* __restrict__ wq,
                               const float* __restrict__ wk,
                               const float* __restrict__ dirs,
                               const float* __restrict__ scale_p) {
    __shared__ float xs[8][Cc];
    __shared__ float sk[8][48];
    const int tid = threadIdx.x;                 // 128
    const int rowBase = blockIdx.x * 8;

    {
        const float4* src = (const float4*)(x + (size_t)rowBase * Cc);
        float4* dst = (float4*)&xs[0][0];
        #pragma unroll
        for (int i = tid; i < 8 * Cc / 4; i += 128) dst[i] = src[i];
    }
    __syncthreads();

    if (tid < 96) {
        const int col = tid % 48;
        const float* __restrict__ w = (tid < 48) ? wq : wk;
        float acc[8];
        #pragma unroll
        for (int r = 0; r < 8; r++) acc[r] = 0.f;
        for (int i = 0; i < Cc; i += 4) {
            float w0 = w[(i + 0) * 48 + col];
            float w1 = w[(i + 1) * 48 + col];
            float w2 = w[(i + 2) * 48 + col];
            float w3 = w[(i + 3) * 48 + col];
            #pragma unroll
            for (int r = 0; r < 8; r++) {
                float4 xv = *(const float4*)&xs[r][i];
                acc[r] = fmaf(xv.x, w0, fmaf(xv.y, w1, fmaf(xv.z, w2, fmaf(xv.w, w3, acc[r]))));
            }
        }
        const int h = col / 3, d = col % 3;
        if (tid < 48) {
            #pragma unroll
            for (int r = 0; r < 8; r++) {
                int row = rowBase + r;
                int b = row / Tt, t = row % Tt;
                g_q3[(((size_t)b * Hh + h) * Tt + t) * 3 + d] = acc[r];
            }
        } else {
            #pragma unroll
            for (int r = 0; r < 8; r++) sk[r][col] = acc[r];
        }
    }
    __syncthreads();

    {
        const int r = tid >> 4, h = tid & 15;
        const float d0 = dirs[h * 3 + 0], d1 = dirs[h * 3 + 1], d2 = dirs[h * 3 + 2];
        const float sc = scale_p[0];
        const float k0 = sk[r][3 * h + 0], k1 = sk[r][3 * h + 1], k2 = sk[r][3 * h + 2];
        const float dot = d0 * k0 + d1 * k1 + d2 * k2;
        int row = rowBase + r;
        int b = row / Tt, t = row % Tt;
        size_t base = (((size_t)b * Hh + h) * Tt + t) * 3;
        g_ka[base + 0] = sc * k0 + d0 * dot;
        g_ka[base + 1] = sc * k1 + d1 * dot;
        g_ka[base + 2] = sc * k2 + d2 * dot;
    }
}

// ---------------------------------------------------------------------------
// Kernel 2/4: fp32 GEMM with packed fma.rn.f32x2, double-buffered pipeline.
// EXACT R10 version (measured 203us): 64x64 tile, BK=8, 64 threads, grid=1024.
// A k-major natural row-pairs; B natural + mov.b64 duplication.
// ---------------------------------------------------------------------------
template <bool SCATTER>
__global__ void __launch_bounds__(64, 7)
gemm_kernel(const float* __restrict__ A,
            const float* __restrict__ Bw,
            float* __restrict__ Cout) {
    const int N = Cc;           // 1024
    const int K = Cc;           // 1024
    __shared__ float As[2][8][64];    // k-major: As[buf][k][row]
    __shared__ float Bs[2][8][72];    // 16B pad per 128B

    const int tid = threadIdx.x;   // 64
    const int tx = tid & 7;
    const int ty = tid >> 3;
    const int rowBase = blockIdx.y * 64;
    const int colBase = blockIdx.x * 64;

    ull acc[4][8];
    #pragma unroll
    for (int p = 0; p < 4; p++)
        #pragma unroll
        for (int j = 0; j < 8; j++) acc[p][j] = 0ULL;

    const int bRow = tid >> 3;               // k within B tile
    const int bColL = (tid & 7) * 8;
    const int bPos = bColL + ((bColL >> 5) << 2);
    const int rb = tx * 8 + ((tx >> 2) << 2);   // padded read base for B

    const float* aSrc = A + (size_t)(rowBase + tid) * K;
    const float* bSrc = Bw + (size_t)bRow * N + colBase + bColL;

    uint32 bDst0 = (uint32)__cvta_generic_to_shared(&Bs[0][bRow][bPos]);
    uint32 bDst1 = (uint32)__cvta_generic_to_shared(&Bs[1][bRow][bPos]);

    // ---- prologue: fill buffer 0 ----
    {
        float4 a0 = *(const float4*)(aSrc + 0);
        float4 a1 = *(const float4*)(aSrc + 4);
        cpasync16(bDst0, bSrc);
        cpasync16(bDst0 + 16, bSrc + 4);
        cpasync_commit();
        As[0][0][tid] = a0.x; As[0][1][tid] = a0.y;
        As[0][2][tid] = a0.z; As[0][3][tid] = a0.w;
        As[0][4][tid] = a1.x; As[0][5][tid] = a1.y;
        As[0][6][tid] = a1.z; As[0][7][tid] = a1.w;
        cpasync_wait0();
    }
    __syncthreads();

    for (int k0 = 0; k0 < K; k0 += 8) {
        const int cur = (k0 >> 3) & 1;
        const int nxt = cur ^ 1;
        const bool has = (k0 + 8) < K;

        float4 n0, n1;
        if (has) {
            uint32 bDstN = nxt ? bDst1 : bDst0;
            cpasync16(bDstN, bSrc + (size_t)(k0 + 8) * N);
            cpasync16(bDstN + 16, bSrc + (size_t)(k0 + 8) * N + 4);
            cpasync_commit();
            n0 = *(const float4*)(aSrc + k0 + 8);
            n1 = *(const float4*)(aSrc + k0 + 12);
        }

        #pragma unroll
        for (int kk = 0; kk < 8; kk++) {
            ulonglong2 av0 = *(const ulonglong2*)&As[cur][kk][ty * 8 + 0];
            ulonglong2 av1 = *(const ulonglong2*)&As[cur][kk][ty * 8 + 4];
            ull ap[4] = {av0.x, av0.y, av1.x, av1.y};
            float4 bv0 = *(const float4*)&Bs[cur][kk][rb + 0];
            float4 bv1 = *(const float4*)&Bs[cur][kk][rb + 4];
            ull bd[8];
            bd[0] = pack2(bv0.x, bv0.x); bd[1] = pack2(bv0.y, bv0.y);
            bd[2] = pack2(bv0.z, bv0.z); bd[3] = pack2(bv0.w, bv0.w);
            bd[4] = pack2(bv1.x, bv1.x); bd[5] = pack2(bv1.y, bv1.y);
            bd[6] = pack2(bv1.z, bv1.z); bd[7] = pack2(bv1.w, bv1.w);
            #pragma unroll
            for (int p = 0; p < 4; p++)
                #pragma unroll
                for (int j = 0; j < 8; j++)
                    FMA2(acc[p][j], ap[p], bd[j]);
        }

        if (has) {
            As[nxt][0][tid] = n0.x; As[nxt][1][tid] = n0.y;
            As[nxt][2][tid] = n0.z; As[nxt][3][tid] = n0.w;
            As[nxt][4][tid] = n1.x; As[nxt][5][tid] = n1.y;
            As[nxt][6][tid] = n1.z; As[nxt][7][tid] = n1.w;
            cpasync_wait0();
            __syncthreads();
        }
    }

    #pragma unroll
    for (int p = 0; p < 4; p++) {
        int m0 = rowBase + ty * 8 + 2 * p;
        #pragma unroll
        for (int j = 0; j < 8; j++) {
            int n = colBase + tx * 8 + j;
            float lo, hi;
            unpack2(acc[p][j], lo, hi);
            if (SCATTER) {
                int h = n >> 6, d = n & (HD - 1);
                int b0i = m0 >> 11, t0 = m0 & (Tt - 1);
                int b1i = (m0 + 1) >> 11, t1 = (m0 + 1) & (Tt - 1);
                g_v[(((size_t)b0i * Hh + h) * Tt + t0) * HD + d] = lo;
                g_v[(((size_t)b1i * Hh + h) * Tt + t1) * HD + d] = hi;
            } else {
                Cout[(size_t)m0 * N + n] = lo;
                Cout[(size_t)(m0 + 1) * N + n] = hi;
            }
        }
    }
}

// ---------------------------------------------------------------------------
// Kernel 3: causal flash attention, d_qk=3 (bias folded into ka), d_v=64.
// 128 threads; thread = (query-pair qA=qp, qB=qp+64) x (32-float d-half).
// Keys stored pre-duplicated in smem ((k,k) ull pairs) so BOTH queries'
// scores come from one packed FMA2 chain. unroll-2 over keys for ILP
// across the expf dependency head.
// ---------------------------------------------------------------------------
__global__ void __launch_bounds__(128)
attn_kernel() {
    __shared__ ull   skk[128][3];      // key tile, duplicated: (k0,k0),(k1,k1),(k2,k2)
    __shared__ float sv[128][HD];      // value tile 32KB
    __shared__ float red[4];

    const int tid  = threadIdx.x;      // 128
    const int qp   = tid >> 1;         // query-pair index: 0..63
    const int half = tid & 1;          // d-half owner
    const int bh   = blockIdx.y;
    const int qt   = gridDim.x - 1 - blockIdx.x;   // heavy tiles first
    const int qAi  = qt * 128 + qp;
    const int qBi  = qAi + 64;

    const float* qpa = g_q3 + ((size_t)bh * Tt + qAi) * 3;
    const float qa0 = qpa[0], qa1 = qpa[1], qa2 = qpa[2];
    const float* qpb = g_q3 + ((size_t)bh * Tt + qBi) * 3;
    const float qb0 = qpb[0], qb1 = qpb[1], qb2 = qpb[2];
    const ull qx2 = pack2(qa0, qb0);
    const ull qy2 = pack2(qa1, qb1);
    const ull qz2 = pack2(qa2, qb2);
    const float qnA = sqrtf(qa0 * qa0 + qa1 * qa1 + qa2 * qa2);
    const float qnB = sqrtf(qb0 * qb0 + qb1 * qb1 + qb2 * qb2);
    const float L2E = 1.4426950408889634f;   // log2(e)
    const ull l2e2 = pack2(L2E, L2E);

    float mA = -1e30f, lA = 0.f, mB = -1e30f, lB = 0.f;
    ull accA[16], accB[16];
    #pragma unroll
    for (int d = 0; d < 16; d++) { accA[d] = 0ULL; accB[d] = 0ULL; }

    const int kmaxTile = qt * 128 + 127;
    const float* kb = g_ka + (size_t)bh * Tt * 3;
    const float* vb = g_v  + (size_t)bh * Tt * HD;

    for (int s0 = 0; s0 <= kmaxTile; s0 += 128) {
        // Key tile (duplicated pairs) + per-tile max |k|
        {
            const float* kpr = kb + (size_t)(s0 + tid) * 3;
            float k0 = kpr[0], k1 = kpr[1], k2 = kpr[2];
            skk[tid][0] = pack2(k0, k0);
            skk[tid][1] = pack2(k1, k1);
            skk[tid][2] = pack2(k2, k2);
            float nk = sqrtf(k0 * k0 + k1 * k1 + k2 * k2);
            #pragma unroll
            for (int o = 16; o; o >>= 1) nk = fmaxf(nk, __shfl_xor_sync(0xffffffffu, nk, o));
            if ((tid & 31) == 0) red[tid >> 5] = nk;
        }
        // Value tile: 2048 float4 / 128 threads
        {
            const float4* vsrc = (const float4*)(vb + (size_t)s0 * HD);
            float4* vdst = (float4*)&sv[0][0];
            #pragma unroll
            for (int i = 0; i < 16; i++) vdst[tid + i * 128] = vsrc[tid + i * 128];
        }
        __syncthreads();

        const int sendA = min(128, qAi - s0 + 1);   // >= 1 always
        const int sendB = min(128, qBi - s0 + 1);   // >= sendA
        const float kmx = fmaxf(fmaxf(red[0], red[1]), fmaxf(red[2], red[3]));

        // Rescale both queries to running tile-bound max (Cauchy-Schwarz)
        {
            const float mnA = fmaxf(mA, qnA * kmx);
            const float cA = __expf(mA - mnA);
            mA = mnA; lA *= cA;
            const ull cpA = pack2(cA, cA);
            #pragma unroll
            for (int d = 0; d < 16; d++) MUL2_IP(accA[d], cpA);
            const float mnB = fmaxf(mB, qnB * kmx);
            const float cB = __expf(mB - mnB);
            mB = mnB; lB *= cB;
            const ull cpB = pack2(cB, cB);
            #pragma unroll
            for (int d = 0; d < 16; d++) MUL2_IP(accB[d], cpB);
        }
        // Packed (-mA*log2e, -mB*log2e) so exp2 arg = sc*log2e - m*log2e in 1 FMA2
        const ull nm2 = pack2(-mA * L2E, -mB * L2E);

        // Loop 1: both queries attend (s < sendA)
        #pragma unroll 2
        for (int s = 0; s < sendA; s++) {
            ull kx = skk[s][0], ky = skk[s][1], kz = skk[s][2];
            ull sc2;
            MUL2_N(sc2, qz2, kz);
            FMA2(sc2, qy2, ky);
            FMA2(sc2, qx2, kx);          // (scA, scB)
            ull e2;
            FMA2_N(e2, sc2, l2e2, nm2);  // (log2e*scA - log2e*mA, ...B)
            float eA, eB;
            unpack2(e2, eA, eB);
            float pA = exp2f(eA);        // MUFU.EX2 each
            float pB = exp2f(eB);
            lA += pA; lB += pB;
            const ull ppA = pack2(pA, pA);
            const ull ppB = pack2(pB, pB);
            const ulonglong2* vr = (const ulonglong2*)sv[s];
            #pragma unroll
            for (int j = 0; j < 8; j++) {
                ulonglong2 vv = vr[2 * j + half];
                FMA2(accA[2 * j + 0], ppA, vv.x);
                FMA2(accA[2 * j + 1], ppA, vv.y);
                FMA2(accB[2 * j + 0], ppB, vv.x);
                FMA2(accB[2 * j + 1], ppB, vv.y);
            }
        }
        // Loop 2: only second query (diagonal tile)
        for (int s = sendA; s < sendB; s++) {
            ull kx = skk[s][0], ky = skk[s][1], kz = skk[s][2];
            float k0, k1, k2, dum;
            unpack2(kx, k0, dum);
            unpack2(ky, k1, dum);
            unpack2(kz, k2, dum);
            float scB = fmaf(qb0, k0, fmaf(qb1, k1, qb2 * k2));
            float pB = __expf(scB - mB); lB += pB;
            const ull ppB = pack2(pB, pB);
            const ulonglong2* vr = (const ulonglong2*)sv[s];
            #pragma unroll
            for (int j = 0; j < 8; j++) {
                ulonglong2 vv = vr[2 * j + half];
                FMA2(accB[2 * j + 0], ppB, vv.x);
                FMA2(accB[2 * j + 1], ppB, vv.y);
            }
        }
        __syncthreads();
    }

    const int b = bh >> 4, h = bh & 15;
    {
        const float invA = 1.f / lA;
        const ull ipA = pack2(invA, invA);
        float4* opA = (float4*)(g_ao + ((size_t)(b * Tt + qAi)) * Cc + h * HD);
        #pragma unroll
        for (int j = 0; j < 8; j++) {
            ull u0 = accA[2 * j + 0], u1 = accA[2 * j + 1];
            MUL2_IP(u0, ipA); MUL2_IP(u1, ipA);
            float4 o;
            unpack2(u0, o.x, o.y);
            unpack2(u1, o.z, o.w);
            opA[2 * j + half] = o;
        }
        const float invB = 1.f / lB;
        const ull ipB = pack2(invB, invB);
        float4* opB = (float4*)(g_ao + ((size_t)(b * Tt + qBi)) * Cc + h * HD);
        #pragma unroll
        for (int j = 0; j < 8; j++) {
            ull u0 = accB[2 * j + 0], u1 = accB[2 * j + 1];
            MUL2_IP(u0, ipB); MUL2_IP(u1, ipB);
            float4 o;
            unpack2(u0, o.x, o.y);
            unpack2(u1, o.z, o.w);
            opB[2 * j + half] = o;
        }
    }
}

// ---------------------------------------------------------------------------
extern "C" void kernel_launch(void* const* d_in, const int* in_sizes, int n_in,
                              void* d_out, int out_size) {
    const float* x     = (const float*)d_in[0];
    const float* wq    = (const float*)d_in[1];
    const float* wk    = (const float*)d_in[2];
    const float* wv    = (const float*)d_in[3];
    const float* wo    = (const float*)d_in[4];
    const float* dirs  = (const float*)d_in[5];
    const float* scale = (const float*)d_in[6];
    float* out = (float*)d_out;

    void *p_ao = nullptr;
    cudaGetSymbolAddress(&p_ao, g_ao);

    // 1. QK projection + key transform
    proj_qk_kernel<<<(Bb * Tt) / 8, 128>>>(x, wq, wk, dirs, scale);

    // 2. V projection GEMM (scatter to (b,h,t,64))
    gemm_kernel<true><<<dim3(Cc / 64, (Bb * Tt) / 64), 64>>>(x, wv, nullptr);

    // 3. Flash attention
    attn_kernel<<<dim3(Tt / 128, Bb * Hh), 128>>>();

    // 4. Output projection GEMM
    gemm_kernel<false><<<dim3(Cc / 64, (Bb * Tt) / 64), 64>>>((const float*)p_ao, wo, out);
}

// round 13
// speedup vs baseline: 1.1300x; 1.0552x over previous
#include <cuda_runtime.h>
#include <cuda_bf16.h>
#include <cstdint>

#define Bb 2
#define Tt 2048
#define Cc 1024
#define Hh 16
#define HD 64

typedef unsigned long long ull;
typedef unsigned int uint32;

// Packed f32x2 helpers (sm_103a): only reachable via PTX *.f32x2.
#define FMA2(d, a, b) \
    asm("fma.rn.f32x2 %0, %1, %2, %0;" : "+l"(d) : "l"(a), "l"(b))
#define MUL2_IP(d, a) \
    asm("mul.rn.f32x2 %0, %1, %0;" : "+l"(d) : "l"(a))
#define FMA2_N(d, a, b, c) \
    asm("fma.rn.f32x2 %0, %1, %2, %3;" : "=l"(d) : "l"(a), "l"(b), "l"(c))
#define MUL2_N(d, a, b) \
    asm("mul.rn.f32x2 %0, %1, %2;" : "=l"(d) : "l"(a), "l"(b))

__device__ __forceinline__ ull pack2(float lo, float hi) {
    ull r;
    asm("mov.b64 %0, {%1, %2};" : "=l"(r) : "f"(lo), "f"(hi));
    return r;
}
__device__ __forceinline__ void unpack2(ull v, float& lo, float& hi) {
    asm("mov.b64 {%0, %1}, %2;" : "=f"(lo), "=f"(hi) : "l"(v));
}
__device__ __forceinline__ void cpasync16(uint32 dst, const void* src) {
    asm volatile("cp.async.cg.shared.global [%0], [%1], 16;" :: "r"(dst), "l"(src) : "memory");
}
__device__ __forceinline__ void cpasync_commit() {
    asm volatile("cp.async.commit_group;" ::: "memory");
}
__device__ __forceinline__ void cpasync_wait0() {
    asm volatile("cp.async.wait_group 0;" ::: "memory");
}

// Scratch (allocation-free rule: __device__ globals)
__device__ float g_q3[(size_t)Bb*Hh*Tt*3];           // (b,h,t,3)
__device__ float g_ka[(size_t)Bb*Hh*Tt*3];           // (b,h,t,3) transformed keys
__device__ float g_v [(size_t)Bb*Hh*Tt*HD];          // (b,h,t,64)
__device__ float g_ao[(size_t)Bb*Tt*Cc];             // (b,t,c) attention output

// ---------------------------------------------------------------------------
// Kernel 1: QK projection + fold (scale*I + d d^T) into K.
// ---------------------------------------------------------------------------
__global__ void proj_qk_kernel(const float* __restrict__ x,
                               const float* __restrict__ wq,
                               const float* __restrict__ wk,
                               const float* __restrict__ dirs,
                               const float* __restrict__ scale_p) {
    __shared__ float xs[8][Cc];
    __shared__ float sk[8][48];
    const int tid = threadIdx.x;                 // 128
    const int rowBase = blockIdx.x * 8;

    {
        const float4* src = (const float4*)(x + (size_t)rowBase * Cc);
        float4* dst = (float4*)&xs[0][0];
        #pragma unroll
        for (int i = tid; i < 8 * Cc / 4; i += 128) dst[i] = src[i];
    }
    __syncthreads();

    if (tid < 96) {
        const int col = tid % 48;
        const float* __restrict__ w = (tid < 48) ? wq : wk;
        float acc[8];
        #pragma unroll
        for (int r = 0; r < 8; r++) acc[r] = 0.f;
        for (int i = 0; i < Cc; i += 4) {
            float w0 = w[(i + 0) * 48 + col];
            float w1 = w[(i + 1) * 48 + col];
            float w2 = w[(i + 2) * 48 + col];
            float w3 = w[(i + 3) * 48 + col];
            #pragma unroll
            for (int r = 0; r < 8; r++) {
                float4 xv = *(const float4*)&xs[r][i];
                acc[r] = fmaf(xv.x, w0, fmaf(xv.y, w1, fmaf(xv.z, w2, fmaf(xv.w, w3, acc[r]))));
            }
        }
        const int h = col / 3, d = col % 3;
        if (tid < 48) {
            #pragma unroll
            for (int r = 0; r < 8; r++) {
                int row = rowBase + r;
                int b = row / Tt, t = row % Tt;
                g_q3[(((size_t)b * Hh + h) * Tt + t) * 3 + d] = acc[r];
            }
        } else {
            #pragma unroll
            for (int r = 0; r < 8; r++) sk[r][col] = acc[r];
        }
    }
    __syncthreads();

    {
        const int r = tid >> 4, h = tid & 15;
        const float d0 = dirs[h * 3 + 0], d1 = dirs[h * 3 + 1], d2 = dirs[h * 3 + 2];
        const float sc = scale_p[0];
        const float k0 = sk[r][3 * h + 0], k1 = sk[r][3 * h + 1], k2 = sk[r][3 * h + 2];
        const float dot = d0 * k0 + d1 * k1 + d2 * k2;
        int row = rowBase + r;
        int b = row / Tt, t = row % Tt;
        size_t base = (((size_t)b * Hh + h) * Tt + t) * 3;
        g_ka[base + 0] = sc * k0 + d0 * dot;
        g_ka[base + 1] = sc * k1 + d1 * dot;
        g_ka[base + 2] = sc * k2 + d2 * dot;
    }
}

// ---------------------------------------------------------------------------
// Kernel 2/4: fp32 GEMM with packed fma.rn.f32x2, double-buffered pipeline.
// EXACT R10/R12 version (measured 203us). Do not touch.
// ---------------------------------------------------------------------------
template <bool SCATTER>
__global__ void __launch_bounds__(64, 7)
gemm_kernel(const float* __restrict__ A,
            const float* __restrict__ Bw,
            float* __restrict__ Cout) {
    const int N = Cc;           // 1024
    const int K = Cc;           // 1024
    __shared__ float As[2][8][64];    // k-major: As[buf][k][row]
    __shared__ float Bs[2][8][72];    // 16B pad per 128B

    const int tid = threadIdx.x;   // 64
    const int tx = tid & 7;
    const int ty = tid >> 3;
    const int rowBase = blockIdx.y * 64;
    const int colBase = blockIdx.x * 64;

    ull acc[4][8];
    #pragma unroll
    for (int p = 0; p < 4; p++)
        #pragma unroll
        for (int j = 0; j < 8; j++) acc[p][j] = 0ULL;

    const int bRow = tid >> 3;               // k within B tile
    const int bColL = (tid & 7) * 8;
    const int bPos = bColL + ((bColL >> 5) << 2);
    const int rb = tx * 8 + ((tx >> 2) << 2);   // padded read base for B

    const float* aSrc = A + (size_t)(rowBase + tid) * K;
    const float* bSrc = Bw + (size_t)bRow * N + colBase + bColL;

    uint32 bDst0 = (uint32)__cvta_generic_to_shared(&Bs[0][bRow][bPos]);
    uint32 bDst1 = (uint32)__cvta_generic_to_shared(&Bs[1][bRow][bPos]);

    // ---- prologue: fill buffer 0 ----
    {
        float4 a0 = *(const float4*)(aSrc + 0);
        float4 a1 = *(const float4*)(aSrc + 4);
        cpasync16(bDst0, bSrc);
        cpasync16(bDst0 + 16, bSrc + 4);
        cpasync_commit();
        As[0][0][tid] = a0.x; As[0][1][tid] = a0.y;
        As[0][2][tid] = a0.z; As[0][3][tid] = a0.w;
        As[0][4][tid] = a1.x; As[0][5][tid] = a1.y;
        As[0][6][tid] = a1.z; As[0][7][tid] = a1.w;
        cpasync_wait0();
    }
    __syncthreads();

    for (int k0 = 0; k0 < K; k0 += 8) {
        const int cur = (k0 >> 3) & 1;
        const int nxt = cur ^ 1;
        const bool has = (k0 + 8) < K;

        float4 n0, n1;
        if (has) {
            uint32 bDstN = nxt ? bDst1 : bDst0;
            cpasync16(bDstN, bSrc + (size_t)(k0 + 8) * N);
            cpasync16(bDstN + 16, bSrc + (size_t)(k0 + 8) * N + 4);
            cpasync_commit();
            n0 = *(const float4*)(aSrc + k0 + 8);
            n1 = *(const float4*)(aSrc + k0 + 12);
        }

        #pragma unroll
        for (int kk = 0; kk < 8; kk++) {
            ulonglong2 av0 = *(const ulonglong2*)&As[cur][kk][ty * 8 + 0];
            ulonglong2 av1 = *(const ulonglong2*)&As[cur][kk][ty * 8 + 4];
            ull ap[4] = {av0.x, av0.y, av1.x, av1.y};
            float4 bv0 = *(const float4*)&Bs[cur][kk][rb + 0];
            float4 bv1 = *(const float4*)&Bs[cur][kk][rb + 4];
            ull bd[8];
            bd[0] = pack2(bv0.x, bv0.x); bd[1] = pack2(bv0.y, bv0.y);
            bd[2] = pack2(bv0.z, bv0.z); bd[3] = pack2(bv0.w, bv0.w);
            bd[4] = pack2(bv1.x, bv1.x); bd[5] = pack2(bv1.y, bv1.y);
            bd[6] = pack2(bv1.z, bv1.z); bd[7] = pack2(bv1.w, bv1.w);
            #pragma unroll
            for (int p = 0; p < 4; p++)
                #pragma unroll
                for (int j = 0; j < 8; j++)
                    FMA2(acc[p][j], ap[p], bd[j]);
        }

        if (has) {
            As[nxt][0][tid] = n0.x; As[nxt][1][tid] = n0.y;
            As[nxt][2][tid] = n0.z; As[nxt][3][tid] = n0.w;
            As[nxt][4][tid] = n1.x; As[nxt][5][tid] = n1.y;
            As[nxt][6][tid] = n1.z; As[nxt][7][tid] = n1.w;
            cpasync_wait0();
            __syncthreads();
        }
    }

    #pragma unroll
    for (int p = 0; p < 4; p++) {
        int m0 = rowBase + ty * 8 + 2 * p;
        #pragma unroll
        for (int j = 0; j < 8; j++) {
            int n = colBase + tx * 8 + j;
            float lo, hi;
            unpack2(acc[p][j], lo, hi);
            if (SCATTER) {
                int h = n >> 6, d = n & (HD - 1);
                int b0i = m0 >> 11, t0 = m0 & (Tt - 1);
                int b1i = (m0 + 1) >> 11, t1 = (m0 + 1) & (Tt - 1);
                g_v[(((size_t)b0i * Hh + h) * Tt + t0) * HD + d] = lo;
                g_v[(((size_t)b1i * Hh + h) * Tt + t1) * HD + d] = hi;
            } else {
                Cout[(size_t)m0 * N + n] = lo;
                Cout[(size_t)(m0 + 1) * N + n] = hi;
            }
        }
    }
}

// ---------------------------------------------------------------------------
// Kernel 3: causal flash attention, d_qk=3 (bias folded into ka), d_v=64.
// 128 threads; thread = (query-pair qA=qp, qB=qp+64) x (32-float d-half).
// 4-KEY BATCHED inner loop: all 4 packed score chains + 8 MUFUs issued
// first (independent -> pipelined), then a pure 128-FMA2 PV block with all
// p-values resolved. Covers the exp dependency head at low occupancy.
// ---------------------------------------------------------------------------
__global__ void __launch_bounds__(128)
attn_kernel() {
    __shared__ ull   skk[128][3];      // key tile, duplicated: (k0,k0),(k1,k1),(k2,k2)
    __shared__ float sv[128][HD];      // value tile 32KB
    __shared__ float red[4];

    const int tid  = threadIdx.x;      // 128
    const int qp   = tid >> 1;         // query-pair index: 0..63
    const int half = tid & 1;          // d-half owner
    const int bh   = blockIdx.y;
    const int qt   = gridDim.x - 1 - blockIdx.x;   // heavy tiles first
    const int qAi  = qt * 128 + qp;
    const int qBi  = qAi + 64;

    const float* qpa = g_q3 + ((size_t)bh * Tt + qAi) * 3;
    const float qa0 = qpa[0], qa1 = qpa[1], qa2 = qpa[2];
    const float* qpb = g_q3 + ((size_t)bh * Tt + qBi) * 3;
    const float qb0 = qpb[0], qb1 = qpb[1], qb2 = qpb[2];
    const ull qx2 = pack2(qa0, qb0);
    const ull qy2 = pack2(qa1, qb1);
    const ull qz2 = pack2(qa2, qb2);
    const float qnA = sqrtf(qa0 * qa0 + qa1 * qa1 + qa2 * qa2);
    const float qnB = sqrtf(qb0 * qb0 + qb1 * qb1 + qb2 * qb2);
    const float L2E = 1.4426950408889634f;   // log2(e)
    const ull l2e2 = pack2(L2E, L2E);

    float mA = -1e30f, lA = 0.f, mB = -1e30f, lB = 0.f;
    ull accA[16], accB[16];
    #pragma unroll
    for (int d = 0; d < 16; d++) { accA[d] = 0ULL; accB[d] = 0ULL; }

    const int kmaxTile = qt * 128 + 127;
    const float* kb = g_ka + (size_t)bh * Tt * 3;
    const float* vb = g_v  + (size_t)bh * Tt * HD;

    for (int s0 = 0; s0 <= kmaxTile; s0 += 128) {
        // Key tile (duplicated pairs) + per-tile max |k|
        {
            const float* kpr = kb + (size_t)(s0 + tid) * 3;
            float k0 = kpr[0], k1 = kpr[1], k2 = kpr[2];
            skk[tid][0] = pack2(k0, k0);
            skk[tid][1] = pack2(k1, k1);
            skk[tid][2] = pack2(k2, k2);
            float nk = sqrtf(k0 * k0 + k1 * k1 + k2 * k2);
            #pragma unroll
            for (int o = 16; o; o >>= 1) nk = fmaxf(nk, __shfl_xor_sync(0xffffffffu, nk, o));
            if ((tid & 31) == 0) red[tid >> 5] = nk;
        }
        // Value tile: 2048 float4 / 128 threads
        {
            const float4* vsrc = (const float4*)(vb + (size_t)s0 * HD);
            float4* vdst = (float4*)&sv[0][0];
            #pragma unroll
            for (int i = 0; i < 16; i++) vdst[tid + i * 128] = vsrc[tid + i * 128];
        }
        __syncthreads();

        const int sendA = min(128, qAi - s0 + 1);   // 128 on off-diagonal tiles
        const int sendB = min(128, qBi - s0 + 1);   // >= sendA
        const float kmx = fmaxf(fmaxf(red[0], red[1]), fmaxf(red[2], red[3]));

        // Rescale both queries to running tile-bound max (Cauchy-Schwarz)
        {
            const float mnA = fmaxf(mA, qnA * kmx);
            const float cA = __expf(mA - mnA);
            mA = mnA; lA *= cA;
            const ull cpA = pack2(cA, cA);
            #pragma unroll
            for (int d = 0; d < 16; d++) MUL2_IP(accA[d], cpA);
            const float mnB = fmaxf(mB, qnB * kmx);
            const float cB = __expf(mB - mnB);
            mB = mnB; lB *= cB;
            const ull cpB = pack2(cB, cB);
            #pragma unroll
            for (int d = 0; d < 16; d++) MUL2_IP(accB[d], cpB);
        }
        // Packed (-mA*log2e, -mB*log2e): exp2 arg = sc*log2e - m*log2e in 1 FMA2
        const ull nm2 = pack2(-mA * L2E, -mB * L2E);

        // Loop 1 batched by 4: scores+exps first (pipelined MUFUs), then
        // a pure-FMA2 PV block with all p resolved.
        int s = 0;
        for (; s + 4 <= sendA; s += 4) {
            ull pp[8];                       // [2u]=ppA(u), [2u+1]=ppB(u)
            #pragma unroll
            for (int u = 0; u < 4; u++) {
                ull sc2;
                MUL2_N(sc2, qz2, skk[s + u][2]);
                FMA2(sc2, qy2, skk[s + u][1]);
                FMA2(sc2, qx2, skk[s + u][0]);
                ull e2;
                FMA2_N(e2, sc2, l2e2, nm2);
                float eA, eB;
                unpack2(e2, eA, eB);
                float pA = exp2f(eA);
                float pB = exp2f(eB);
                lA += pA; lB += pB;
                pp[2 * u + 0] = pack2(pA, pA);
                pp[2 * u + 1] = pack2(pB, pB);
            }
            #pragma unroll
            for (int u = 0; u < 4; u++) {
                const ulonglong2* vr = (const ulonglong2*)sv[s + u];
                const ull ppA = pp[2 * u + 0], ppB = pp[2 * u + 1];
                #pragma unroll
                for (int j = 0; j < 8; j++) {
                    ulonglong2 vv = vr[2 * j + half];
                    FMA2(accA[2 * j + 0], ppA, vv.x);
                    FMA2(accA[2 * j + 1], ppA, vv.y);
                    FMA2(accB[2 * j + 0], ppB, vv.x);
                    FMA2(accB[2 * j + 1], ppB, vv.y);
                }
            }
        }
        // Loop 1 remainder (diagonal tiles only)
        for (; s < sendA; s++) {
            ull sc2;
            MUL2_N(sc2, qz2, skk[s][2]);
            FMA2(sc2, qy2, skk[s][1]);
            FMA2(sc2, qx2, skk[s][0]);
            ull e2;
            FMA2_N(e2, sc2, l2e2, nm2);
            float eA, eB;
            unpack2(e2, eA, eB);
            float pA = exp2f(eA);
            float pB = exp2f(eB);
            lA += pA; lB += pB;
            const ull ppA = pack2(pA, pA);
            const ull ppB = pack2(pB, pB);
            const ulonglong2* vr = (const ulonglong2*)sv[s];
            #pragma unroll
            for (int j = 0; j < 8; j++) {
                ulonglong2 vv = vr[2 * j + half];
                FMA2(accA[2 * j + 0], ppA, vv.x);
                FMA2(accA[2 * j + 1], ppA, vv.y);
                FMA2(accB[2 * j + 0], ppB, vv.x);
                FMA2(accB[2 * j + 1], ppB, vv.y);
            }
        }
        // Loop 2: only second query (diagonal tiles only)
        for (int s2 = sendA; s2 < sendB; s2++) {
            float k0, k1, k2, dum;
            unpack2(skk[s2][0], k0, dum);
            unpack2(skk[s2][1], k1, dum);
            unpack2(skk[s2][2], k2, dum);
            float scB = fmaf(qb0, k0, fmaf(qb1, k1, qb2 * k2));
            float pB = __expf(scB - mB); lB += pB;
            const ull ppB = pack2(pB, pB);
            const ulonglong2* vr = (const ulonglong2*)sv[s2];
            #pragma unroll
            for (int j = 0; j < 8; j++) {
                ulonglong2 vv = vr[2 * j + half];
                FMA2(accB[2 * j + 0], ppB, vv.x);
                FMA2(accB[2 * j + 1], ppB, vv.y);
            }
        }
        __syncthreads();
    }

    const int b = bh >> 4, h = bh & 15;
    {
        const float invA = 1.f / lA;
        const ull ipA = pack2(invA, invA);
        float4* opA = (float4*)(g_ao + ((size_t)(b * Tt + qAi)) * Cc + h * HD);
        #pragma unroll
        for (int j = 0; j < 8; j++) {
            ull u0 = accA[2 * j + 0], u1 = accA[2 * j + 1];
            MUL2_IP(u0, ipA); MUL2_IP(u1, ipA);
            float4 o;
            unpack2(u0, o.x, o.y);
            unpack2(u1, o.z, o.w);
            opA[2 * j + half] = o;
        }
        const float invB = 1.f / lB;
        const ull ipB = pack2(invB, invB);
        float4* opB = (float4*)(g_ao + ((size_t)(b * Tt + qBi)) * Cc + h * HD);
        #pragma unroll
        for (int j = 0; j < 8; j++) {
            ull u0 = accB[2 * j + 0], u1 = accB[2 * j + 1];
            MUL2_IP(u0, ipB); MUL2_IP(u1, ipB);
            float4 o;
            unpack2(u0, o.x, o.y);
            unpack2(u1, o.z, o.w);
            opB[2 * j + half] = o;
        }
    }
}

// ---------------------------------------------------------------------------
extern "C" void kernel_launch(void* const* d_in, const int* in_sizes, int n_in,
                              void* d_out, int out_size) {
    const float* x     = (const float*)d_in[0];
    const float* wq    = (const float*)d_in[1];
    const float* wk    = (const float*)d_in[2];
    const float* wv    = (const float*)d_in[3];
    const float* wo    = (const float*)d_in[4];
    const float* dirs  = (const float*)d_in[5];
    const float* scale = (const float*)d_in[6];
    float* out = (float*)d_out;

    void *p_ao = nullptr;
    cudaGetSymbolAddress(&p_ao, g_ao);

    // 1. QK projection + key transform
    proj_qk_kernel<<<(Bb * Tt) / 8, 128>>>(x, wq, wk, dirs, scale);

    // 2. V projection GEMM (scatter to (b,h,t,64))
    gemm_kernel<true><<<dim3(Cc / 64, (Bb * Tt) / 64), 64>>>(x, wv, nullptr);

    // 3. Flash attention
    attn_kernel<<<dim3(Tt / 128, Bb * Hh), 128>>>();

    // 4. Output projection GEMM
    gemm_kernel<false><<<dim3(Cc / 64, (Bb * Tt) / 64), 64>>>((const float*)p_ao, wo, out);
}

// round 14
// speedup vs baseline: 1.1361x; 1.0054x over previous
#include <cuda_runtime.h>
#include <cuda_bf16.h>
#include <cstdint>

#define Bb 2
#define Tt 2048
#define Cc 1024
#define Hh 16
#define HD 64

typedef unsigned long long ull;
typedef unsigned int uint32;

// Packed f32x2 helpers (sm_103a): only reachable via PTX *.f32x2.
#define FMA2(d, a, b) \
    asm("fma.rn.f32x2 %0, %1, %2, %0;" : "+l"(d) : "l"(a), "l"(b))
#define MUL2_IP(d, a) \
    asm("mul.rn.f32x2 %0, %1, %0;" : "+l"(d) : "l"(a))
#define FMA2_N(d, a, b, c) \
    asm("fma.rn.f32x2 %0, %1, %2, %3;" : "=l"(d) : "l"(a), "l"(b), "l"(c))
#define MUL2_N(d, a, b) \
    asm("mul.rn.f32x2 %0, %1, %2;" : "=l"(d) : "l"(a), "l"(b))

__device__ __forceinline__ ull pack2(float lo, float hi) {
    ull r;
    asm("mov.b64 %0, {%1, %2};" : "=l"(r) : "f"(lo), "f"(hi));
    return r;
}
__device__ __forceinline__ void unpack2(ull v, float& lo, float& hi) {
    asm("mov.b64 {%0, %1}, %2;" : "=f"(lo), "=f"(hi) : "l"(v));
}
__device__ __forceinline__ void cpasync16(uint32 dst, const void* src) {
    asm volatile("cp.async.cg.shared.global [%0], [%1], 16;" :: "r"(dst), "l"(src) : "memory");
}
__device__ __forceinline__ void cpasync_commit() {
    asm volatile("cp.async.commit_group;" ::: "memory");
}
__device__ __forceinline__ void cpasync_wait0() {
    asm volatile("cp.async.wait_group 0;" ::: "memory");
}

// Scratch (allocation-free rule: __device__ globals)
__device__ float g_q3[(size_t)Bb*Hh*Tt*3];           // (b,h,t,3)
__device__ float g_ka[(size_t)Bb*Hh*Tt*3];           // (b,h,t,3) transformed keys
__device__ float g_v [(size_t)Bb*Hh*Tt*HD];          // (b,h,t,64)
__device__ float g_ao[(size_t)Bb*Tt*Cc];             // (b,t,c) attention output
__device__ float g_pacc[2*(size_t)Bb*Hh*Tt*HD];      // split partial acc (unnormalized)
__device__ float g_pml[2*(size_t)Bb*Hh*Tt*2];        // split partial (m, l)

// ---------------------------------------------------------------------------
// Kernel 1: QK projection + fold (scale*I + d d^T) into K.
// ---------------------------------------------------------------------------
__global__ void proj_qk_kernel(const float* __restrict__ x,
                               const float* __restrict__ wq,
                               const float* __restrict__ wk,
                               const float* __restrict__ dirs,
                               const float* __restrict__ scale_p) {
    __shared__ float xs[8][Cc];
    __shared__ float sk[8][48];
    const int tid = threadIdx.x;                 // 128
    const int rowBase = blockIdx.x * 8;

    {
        const float4* src = (const float4*)(x + (size_t)rowBase * Cc);
        float4* dst = (float4*)&xs[0][0];
        #pragma unroll
        for (int i = tid; i < 8 * Cc / 4; i += 128) dst[i] = src[i];
    }
    __syncthreads();

    if (tid < 96) {
        const int col = tid % 48;
        const float* __restrict__ w = (tid < 48) ? wq : wk;
        float acc[8];
        #pragma unroll
        for (int r = 0; r < 8; r++) acc[r] = 0.f;
        for (int i = 0; i < Cc; i += 4) {
            float w0 = w[(i + 0) * 48 + col];
            float w1 = w[(i + 1) * 48 + col];
            float w2 = w[(i + 2) * 48 + col];
            float w3 = w[(i + 3) * 48 + col];
            #pragma unroll
            for (int r = 0; r < 8; r++) {
                float4 xv = *(const float4*)&xs[r][i];
                acc[r] = fmaf(xv.x, w0, fmaf(xv.y, w1, fmaf(xv.z, w2, fmaf(xv.w, w3, acc[r]))));
            }
        }
        const int h = col / 3, d = col % 3;
        if (tid < 48) {
            #pragma unroll
            for (int r = 0; r < 8; r++) {
                int row = rowBase + r;
                int b = row / Tt, t = row % Tt;
                g_q3[(((size_t)b * Hh + h) * Tt + t) * 3 + d] = acc[r];
            }
        } else {
            #pragma unroll
            for (int r = 0; r < 8; r++) sk[r][col] = acc[r];
        }
    }
    __syncthreads();

    {
        const int r = tid >> 4, h = tid & 15;
        const float d0 = dirs[h * 3 + 0], d1 = dirs[h * 3 + 1], d2 = dirs[h * 3 + 2];
        const float sc = scale_p[0];
        const float k0 = sk[r][3 * h + 0], k1 = sk[r][3 * h + 1], k2 = sk[r][3 * h + 2];
        const float dot = d0 * k0 + d1 * k1 + d2 * k2;
        int row = rowBase + r;
        int b = row / Tt, t = row % Tt;
        size_t base = (((size_t)b * Hh + h) * Tt + t) * 3;
        g_ka[base + 0] = sc * k0 + d0 * dot;
        g_ka[base + 1] = sc * k1 + d1 * dot;
        g_ka[base + 2] = sc * k2 + d2 * dot;
    }
}

// ---------------------------------------------------------------------------
// Kernel 2/4: fp32 GEMM with packed fma.rn.f32x2, double-buffered pipeline.
// EXACT R10/R12 version (measured 203us). Do not touch.
// ---------------------------------------------------------------------------
template <bool SCATTER>
__global__ void __launch_bounds__(64, 7)
gemm_kernel(const float* __restrict__ A,
            const float* __restrict__ Bw,
            float* __restrict__ Cout) {
    const int N = Cc;           // 1024
    const int K = Cc;           // 1024
    __shared__ float As[2][8][64];    // k-major: As[buf][k][row]
    __shared__ float Bs[2][8][72];    // 16B pad per 128B

    const int tid = threadIdx.x;   // 64
    const int tx = tid & 7;
    const int ty = tid >> 3;
    const int rowBase = blockIdx.y * 64;
    const int colBase = blockIdx.x * 64;

    ull acc[4][8];
    #pragma unroll
    for (int p = 0; p < 4; p++)
        #pragma unroll
        for (int j = 0; j < 8; j++) acc[p][j] = 0ULL;

    const int bRow = tid >> 3;               // k within B tile
    const int bColL = (tid & 7) * 8;
    const int bPos = bColL + ((bColL >> 5) << 2);
    const int rb = tx * 8 + ((tx >> 2) << 2);   // padded read base for B

    const float* aSrc = A + (size_t)(rowBase + tid) * K;
    const float* bSrc = Bw + (size_t)bRow * N + colBase + bColL;

    uint32 bDst0 = (uint32)__cvta_generic_to_shared(&Bs[0][bRow][bPos]);
    uint32 bDst1 = (uint32)__cvta_generic_to_shared(&Bs[1][bRow][bPos]);

    // ---- prologue: fill buffer 0 ----
    {
        float4 a0 = *(const float4*)(aSrc + 0);
        float4 a1 = *(const float4*)(aSrc + 4);
        cpasync16(bDst0, bSrc);
        cpasync16(bDst0 + 16, bSrc + 4);
        cpasync_commit();
        As[0][0][tid] = a0.x; As[0][1][tid] = a0.y;
        As[0][2][tid] = a0.z; As[0][3][tid] = a0.w;
        As[0][4][tid] = a1.x; As[0][5][tid] = a1.y;
        As[0][6][tid] = a1.z; As[0][7][tid] = a1.w;
        cpasync_wait0();
    }
    __syncthreads();

    for (int k0 = 0; k0 < K; k0 += 8) {
        const int cur = (k0 >> 3) & 1;
        const int nxt = cur ^ 1;
        const bool has = (k0 + 8) < K;

        float4 n0, n1;
        if (has) {
            uint32 bDstN = nxt ? bDst1 : bDst0;
            cpasync16(bDstN, bSrc + (size_t)(k0 + 8) * N);
            cpasync16(bDstN + 16, bSrc + (size_t)(k0 + 8) * N + 4);
            cpasync_commit();
            n0 = *(const float4*)(aSrc + k0 + 8);
            n1 = *(const float4*)(aSrc + k0 + 12);
        }

        #pragma unroll
        for (int kk = 0; kk < 8; kk++) {
            ulonglong2 av0 = *(const ulonglong2*)&As[cur][kk][ty * 8 + 0];
            ulonglong2 av1 = *(const ulonglong2*)&As[cur][kk][ty * 8 + 4];
            ull ap[4] = {av0.x, av0.y, av1.x, av1.y};
            float4 bv0 = *(const float4*)&Bs[cur][kk][rb + 0];
            float4 bv1 = *(const float4*)&Bs[cur][kk][rb + 4];
            ull bd[8];
            bd[0] = pack2(bv0.x, bv0.x); bd[1] = pack2(bv0.y, bv0.y);
            bd[2] = pack2(bv0.z, bv0.z); bd[3] = pack2(bv0.w, bv0.w);
            bd[4] = pack2(bv1.x, bv1.x); bd[5] = pack2(bv1.y, bv1.y);
            bd[6] = pack2(bv1.z, bv1.z); bd[7] = pack2(bv1.w, bv1.w);
            #pragma unroll
            for (int p = 0; p < 4; p++)
                #pragma unroll
                for (int j = 0; j < 8; j++)
                    FMA2(acc[p][j], ap[p], bd[j]);
        }

        if (has) {
            As[nxt][0][tid] = n0.x; As[nxt][1][tid] = n0.y;
            As[nxt][2][tid] = n0.z; As[nxt][3][tid] = n0.w;
            As[nxt][4][tid] = n1.x; As[nxt][5][tid] = n1.y;
            As[nxt][6][tid] = n1.z; As[nxt][7][tid] = n1.w;
            cpasync_wait0();
            __syncthreads();
        }
    }

    #pragma unroll
    for (int p = 0; p < 4; p++) {
        int m0 = rowBase + ty * 8 + 2 * p;
        #pragma unroll
        for (int j = 0; j < 8; j++) {
            int n = colBase + tx * 8 + j;
            float lo, hi;
            unpack2(acc[p][j], lo, hi);
            if (SCATTER) {
                int h = n >> 6, d = n & (HD - 1);
                int b0i = m0 >> 11, t0 = m0 & (Tt - 1);
                int b1i = (m0 + 1) >> 11, t1 = (m0 + 1) & (Tt - 1);
                g_v[(((size_t)b0i * Hh + h) * Tt + t0) * HD + d] = lo;
                g_v[(((size_t)b1i * Hh + h) * Tt + t1) * HD + d] = hi;
            } else {
                Cout[(size_t)m0 * N + n] = lo;
                Cout[(size_t)(m0 + 1) * N + n] = hi;
            }
        }
    }
}

// ---------------------------------------------------------------------------
// Kernel 3: causal flash attention, SPLIT-K over key-tile parity.
// blockIdx.y = bh*2 + split; split handles key-tiles s0 = split*128, +256.
// 128 threads; thread = (query-pair qA=qp, qB=qp+64) x (32-float d-half).
// 4-key batched inner loop. Partials (m, l, unnormalized acc) -> scratch.
// ---------------------------------------------------------------------------
__global__ void __launch_bounds__(128)
attn_kernel() {
    __shared__ ull   skk[128][3];      // key tile, duplicated pairs
    __shared__ float sv[128][HD];      // value tile 32KB
    __shared__ float red[4];

    const int tid   = threadIdx.x;     // 128
    const int qp    = tid >> 1;        // query-pair index: 0..63
    const int half  = tid & 1;         // d-half owner
    const int bh    = blockIdx.y >> 1;
    const int split = blockIdx.y & 1;
    const int qt    = gridDim.x - 1 - blockIdx.x;   // heavy tiles first
    const int qAi   = qt * 128 + qp;
    const int qBi   = qAi + 64;

    const float* qpa = g_q3 + ((size_t)bh * Tt + qAi) * 3;
    const float qa0 = qpa[0], qa1 = qpa[1], qa2 = qpa[2];
    const float* qpb = g_q3 + ((size_t)bh * Tt + qBi) * 3;
    const float qb0 = qpb[0], qb1 = qpb[1], qb2 = qpb[2];
    const ull qx2 = pack2(qa0, qb0);
    const ull qy2 = pack2(qa1, qb1);
    const ull qz2 = pack2(qa2, qb2);
    const float qnA = sqrtf(qa0 * qa0 + qa1 * qa1 + qa2 * qa2);
    const float qnB = sqrtf(qb0 * qb0 + qb1 * qb1 + qb2 * qb2);
    const float L2E = 1.4426950408889634f;   // log2(e)
    const ull l2e2 = pack2(L2E, L2E);

    float mA = -1e30f, lA = 0.f, mB = -1e30f, lB = 0.f;
    ull accA[16], accB[16];
    #pragma unroll
    for (int d = 0; d < 16; d++) { accA[d] = 0ULL; accB[d] = 0ULL; }

    const int kmaxTile = qt * 128 + 127;
    const float* kb = g_ka + (size_t)bh * Tt * 3;
    const float* vb = g_v  + (size_t)bh * Tt * HD;

    for (int s0 = split * 128; s0 <= kmaxTile; s0 += 256) {
        // Key tile (duplicated pairs) + per-tile max |k|
        {
            const float* kpr = kb + (size_t)(s0 + tid) * 3;
            float k0 = kpr[0], k1 = kpr[1], k2 = kpr[2];
            skk[tid][0] = pack2(k0, k0);
            skk[tid][1] = pack2(k1, k1);
            skk[tid][2] = pack2(k2, k2);
            float nk = sqrtf(k0 * k0 + k1 * k1 + k2 * k2);
            #pragma unroll
            for (int o = 16; o; o >>= 1) nk = fmaxf(nk, __shfl_xor_sync(0xffffffffu, nk, o));
            if ((tid & 31) == 0) red[tid >> 5] = nk;
        }
        // Value tile: 2048 float4 / 128 threads
        {
            const float4* vsrc = (const float4*)(vb + (size_t)s0 * HD);
            float4* vdst = (float4*)&sv[0][0];
            #pragma unroll
            for (int i = 0; i < 16; i++) vdst[tid + i * 128] = vsrc[tid + i * 128];
        }
        __syncthreads();

        const int sendA = min(128, qAi - s0 + 1);   // 128 on off-diagonal tiles
        const int sendB = min(128, qBi - s0 + 1);   // >= sendA
        const float kmx = fmaxf(fmaxf(red[0], red[1]), fmaxf(red[2], red[3]));

        // Rescale both queries to running tile-bound max (Cauchy-Schwarz)
        {
            const float mnA = fmaxf(mA, qnA * kmx);
            const float cA = __expf(mA - mnA);
            mA = mnA; lA *= cA;
            const ull cpA = pack2(cA, cA);
            #pragma unroll
            for (int d = 0; d < 16; d++) MUL2_IP(accA[d], cpA);
            const float mnB = fmaxf(mB, qnB * kmx);
            const float cB = __expf(mB - mnB);
            mB = mnB; lB *= cB;
            const ull cpB = pack2(cB, cB);
            #pragma unroll
            for (int d = 0; d < 16; d++) MUL2_IP(accB[d], cpB);
        }
        const ull nm2 = pack2(-mA * L2E, -mB * L2E);

        // Loop 1 batched by 4: scores+exps first (pipelined MUFUs), then
        // a pure-FMA2 PV block with all p resolved.
        int s = 0;
        for (; s + 4 <= sendA; s += 4) {
            ull pp[8];
            #pragma unroll
            for (int u = 0; u < 4; u++) {
                ull sc2;
                MUL2_N(sc2, qz2, skk[s + u][2]);
                FMA2(sc2, qy2, skk[s + u][1]);
                FMA2(sc2, qx2, skk[s + u][0]);
                ull e2;
                FMA2_N(e2, sc2, l2e2, nm2);
                float eA, eB;
                unpack2(e2, eA, eB);
                float pA = exp2f(eA);
                float pB = exp2f(eB);
                lA += pA; lB += pB;
                pp[2 * u + 0] = pack2(pA, pA);
                pp[2 * u + 1] = pack2(pB, pB);
            }
            #pragma unroll
            for (int u = 0; u < 4; u++) {
                const ulonglong2* vr = (const ulonglong2*)sv[s + u];
                const ull ppA = pp[2 * u + 0], ppB = pp[2 * u + 1];
                #pragma unroll
                for (int j = 0; j < 8; j++) {
                    ulonglong2 vv = vr[2 * j + half];
                    FMA2(accA[2 * j + 0], ppA, vv.x);
                    FMA2(accA[2 * j + 1], ppA, vv.y);
                    FMA2(accB[2 * j + 0], ppB, vv.x);
                    FMA2(accB[2 * j + 1], ppB, vv.y);
                }
            }
        }
        // Loop 1 remainder (diagonal tile only)
        for (; s < sendA; s++) {
            ull sc2;
            MUL2_N(sc2, qz2, skk[s][2]);
            FMA2(sc2, qy2, skk[s][1]);
            FMA2(sc2, qx2, skk[s][0]);
            ull e2;
            FMA2_N(e2, sc2, l2e2, nm2);
            float eA, eB;
            unpack2(e2, eA, eB);
            float pA = exp2f(eA);
            float pB = exp2f(eB);
            lA += pA; lB += pB;
            const ull ppA = pack2(pA, pA);
            const ull ppB = pack2(pB, pB);
            const ulonglong2* vr = (const ulonglong2*)sv[s];
            #pragma unroll
            for (int j = 0; j < 8; j++) {
                ulonglong2 vv = vr[2 * j + half];
                FMA2(accA[2 * j + 0], ppA, vv.x);
                FMA2(accA[2 * j + 1], ppA, vv.y);
                FMA2(accB[2 * j + 0], ppB, vv.x);
                FMA2(accB[2 * j + 1], ppB, vv.y);
            }
        }
        // Loop 2: only second query (diagonal tile only)
        for (int s2 = sendA; s2 < sendB; s2++) {
            float k0, k1, k2, dum;
            unpack2(skk[s2][0], k0, dum);
            unpack2(skk[s2][1], k1, dum);
            unpack2(skk[s2][2], k2, dum);
            float scB = fmaf(qb0, k0, fmaf(qb1, k1, qb2 * k2));
            float pB = __expf(scB - mB); lB += pB;
            const ull ppB = pack2(pB, pB);
            const ulonglong2* vr = (const ulonglong2*)sv[s2];
            #pragma unroll
            for (int j = 0; j < 8; j++) {
                ulonglong2 vv = vr[2 * j + half];
                FMA2(accB[2 * j + 0], ppB, vv.x);
                FMA2(accB[2 * j + 1], ppB, vv.y);
            }
        }
        __syncthreads();
    }

    // Write UNNORMALIZED partials + (m, l) to scratch
    {
        const size_t pbase = ((size_t)split * (Bb * Hh) + bh) * Tt;
        float4* pA4 = (float4*)(g_pacc + (pbase + qAi) * HD);
        float4* pB4 = (float4*)(g_pacc + (pbase + qBi) * HD);
        #pragma unroll
        for (int j = 0; j < 8; j++) {
            float4 oa, ob;
            unpack2(accA[2 * j + 0], oa.x, oa.y);
            unpack2(accA[2 * j + 1], oa.z, oa.w);
            pA4[2 * j + half] = oa;
            unpack2(accB[2 * j + 0], ob.x, ob.y);
            unpack2(accB[2 * j + 1], ob.z, ob.w);
            pB4[2 * j + half] = ob;
        }
        if (half == 0) {
            float* mlA = g_pml + (pbase + qAi) * 2;
            mlA[0] = mA; mlA[1] = lA;
            float* mlB = g_pml + (pbase + qBi) * 2;
            mlB[0] = mB; mlB[1] = lB;
        }
    }
}

// ---------------------------------------------------------------------------
// Kernel 3b: split reduce. Thread = (bh, q, quarter-of-64).
// out = (c0*acc0 + c1*acc1) / (c0*l0 + c1*l1), c_i = exp(m_i - max(m0,m1)).
// ---------------------------------------------------------------------------
__global__ void __launch_bounds__(256)
attn_reduce_kernel() {
    const int gid = blockIdx.x * 256 + threadIdx.x;   // 32*2048*4 total
    const int quarter = gid & 3;
    const int q = (gid >> 2) & (Tt - 1);
    const int bh = gid >> 13;                          // / (2048*4)

    const size_t i0 = ((size_t)bh * Tt + q);
    const size_t i1 = ((size_t)(Bb * Hh) + bh) * Tt + q;
    const float m0 = g_pml[i0 * 2 + 0], l0 = g_pml[i0 * 2 + 1];
    const float m1 = g_pml[i1 * 2 + 0], l1 = g_pml[i1 * 2 + 1];
    const float M = fmaxf(m0, m1);
    const float c0 = __expf(m0 - M);
    const float c1 = __expf(m1 - M);
    const float inv = 1.f / (c0 * l0 + c1 * l1);
    const float w0 = c0 * inv, w1 = c1 * inv;

    const float4* a0 = (const float4*)(g_pacc + i0 * HD + quarter * 16);
    const float4* a1 = (const float4*)(g_pacc + i1 * HD + quarter * 16);
    const int b = bh >> 4, h = bh & 15;
    float4* op = (float4*)(g_ao + ((size_t)(b * Tt + q)) * Cc + h * HD + quarter * 16);
    #pragma unroll
    for (int j = 0; j < 4; j++) {
        float4 v0 = a0[j], v1 = a1[j];
        float4 o;
        o.x = v0.x * w0 + v1.x * w1;
        o.y = v0.y * w0 + v1.y * w1;
        o.z = v0.z * w0 + v1.z * w1;
        o.w = v0.w * w0 + v1.w * w1;
        op[j] = o;
    }
}

// ---------------------------------------------------------------------------
extern "C" void kernel_launch(void* const* d_in, const int* in_sizes, int n_in,
                              void* d_out, int out_size) {
    const float* x     = (const float*)d_in[0];
    const float* wq    = (const float*)d_in[1];
    const float* wk    = (const float*)d_in[2];
    const float* wv    = (const float*)d_in[3];
    const float* wo    = (const float*)d_in[4];
    const float* dirs  = (const float*)d_in[5];
    const float* scale = (const float*)d_in[6];
    float* out = (float*)d_out;

    void *p_ao = nullptr;
    cudaGetSymbolAddress(&p_ao, g_ao);

    // 1. QK projection + key transform
    proj_qk_kernel<<<(Bb * Tt) / 8, 128>>>(x, wq, wk, dirs, scale);

    // 2. V projection GEMM (scatter to (b,h,t,64))
    gemm_kernel<true><<<dim3(Cc / 64, (Bb * Tt) / 64), 64>>>(x, wv, nullptr);

    // 3. Flash attention, split-K by key-tile parity (2x occupancy)
    attn_kernel<<<dim3(Tt / 128, Bb * Hh * 2), 128>>>();
    attn_reduce_kernel<<<(Bb * Hh * Tt * 4) / 256, 256>>>();

    // 4. Output projection GEMM
    gemm_kernel<false><<<dim3(Cc / 64, (Bb * Tt) / 64), 64>>>((const float*)p_ao, wo, out);
}

// round 15
// speedup vs baseline: 1.1362x; 1.0001x over previous
#include <cuda_runtime.h>
#include <cuda_bf16.h>
#include <cstdint>

#define Bb 2
#define Tt 2048
#define Cc 1024
#define Hh 16
#define HD 64

typedef unsigned long long ull;
typedef unsigned int uint32;

// Packed f32x2 helpers (sm_103a): only reachable via PTX *.f32x2.
#define FMA2(d, a, b) \
    asm("fma.rn.f32x2 %0, %1, %2, %0;" : "+l"(d) : "l"(a), "l"(b))
#define MUL2_IP(d, a) \
    asm("mul.rn.f32x2 %0, %1, %0;" : "+l"(d) : "l"(a))
#define FMA2_N(d, a, b, c) \
    asm("fma.rn.f32x2 %0, %1, %2, %3;" : "=l"(d) : "l"(a), "l"(b), "l"(c))
#define MUL2_N(d, a, b) \
    asm("mul.rn.f32x2 %0, %1, %2;" : "=l"(d) : "l"(a), "l"(b))

__device__ __forceinline__ ull pack2(float lo, float hi) {
    ull r;
    asm("mov.b64 %0, {%1, %2};" : "=l"(r) : "f"(lo), "f"(hi));
    return r;
}
__device__ __forceinline__ void unpack2(ull v, float& lo, float& hi) {
    asm("mov.b64 {%0, %1}, %2;" : "=f"(lo), "=f"(hi) : "l"(v));
}
__device__ __forceinline__ void cpasync16(uint32 dst, const void* src) {
    asm volatile("cp.async.cg.shared.global [%0], [%1], 16;" :: "r"(dst), "l"(src) : "memory");
}
__device__ __forceinline__ void cpasync_commit() {
    asm volatile("cp.async.commit_group;" ::: "memory");
}
__device__ __forceinline__ void cpasync_wait0() {
    asm volatile("cp.async.wait_group 0;" ::: "memory");
}

// Scratch (allocation-free rule: __device__ globals)
__device__ float g_q3[(size_t)Bb*Hh*Tt*3];           // (b,h,t,3)
__device__ float g_ka[(size_t)Bb*Hh*Tt*3];           // (b,h,t,3) transformed keys
__device__ float g_v [(size_t)Bb*Hh*Tt*HD];          // (b,h,t,64)
__device__ float g_ao[(size_t)Bb*Tt*Cc];             // (b,t,c) attention output
__device__ float g_pacc[2*(size_t)Bb*Hh*Tt*HD];      // split partial acc (unnormalized)
__device__ float g_pml[2*(size_t)Bb*Hh*Tt*2];        // split partial (m, l)

// ---------------------------------------------------------------------------
// Kernel 1: QK projection + fold (scale*I + d d^T) into K.
// ---------------------------------------------------------------------------
__global__ void proj_qk_kernel(const float* __restrict__ x,
                               const float* __restrict__ wq,
                               const float* __restrict__ wk,
                               const float* __restrict__ dirs,
                               const float* __restrict__ scale_p) {
    __shared__ float xs[8][Cc];
    __shared__ float sk[8][48];
    const int tid = threadIdx.x;                 // 128
    const int rowBase = blockIdx.x * 8;

    {
        const float4* src = (const float4*)(x + (size_t)rowBase * Cc);
        float4* dst = (float4*)&xs[0][0];
        #pragma unroll
        for (int i = tid; i < 8 * Cc / 4; i += 128) dst[i] = src[i];
    }
    __syncthreads();

    if (tid < 96) {
        const int col = tid % 48;
        const float* __restrict__ w = (tid < 48) ? wq : wk;
        float acc[8];
        #pragma unroll
        for (int r = 0; r < 8; r++) acc[r] = 0.f;
        for (int i = 0; i < Cc; i += 4) {
            float w0 = w[(i + 0) * 48 + col];
            float w1 = w[(i + 1) * 48 + col];
            float w2 = w[(i + 2) * 48 + col];
            float w3 = w[(i + 3) * 48 + col];
            #pragma unroll
            for (int r = 0; r < 8; r++) {
                float4 xv = *(const float4*)&xs[r][i];
                acc[r] = fmaf(xv.x, w0, fmaf(xv.y, w1, fmaf(xv.z, w2, fmaf(xv.w, w3, acc[r]))));
            }
        }
        const int h = col / 3, d = col % 3;
        if (tid < 48) {
            #pragma unroll
            for (int r = 0; r < 8; r++) {
                int row = rowBase + r;
                int b = row / Tt, t = row % Tt;
                g_q3[(((size_t)b * Hh + h) * Tt + t) * 3 + d] = acc[r];
            }
        } else {
            #pragma unroll
            for (int r = 0; r < 8; r++) sk[r][col] = acc[r];
        }
    }
    __syncthreads();

    {
        const int r = tid >> 4, h = tid & 15;
        const float d0 = dirs[h * 3 + 0], d1 = dirs[h * 3 + 1], d2 = dirs[h * 3 + 2];
        const float sc = scale_p[0];
        const float k0 = sk[r][3 * h + 0], k1 = sk[r][3 * h + 1], k2 = sk[r][3 * h + 2];
        const float dot = d0 * k0 + d1 * k1 + d2 * k2;
        int row = rowBase + r;
        int b = row / Tt, t = row % Tt;
        size_t base = (((size_t)b * Hh + h) * Tt + t) * 3;
        g_ka[base + 0] = sc * k0 + d0 * dot;
        g_ka[base + 1] = sc * k1 + d1 * dot;
        g_ka[base + 2] = sc * k2 + d2 * dot;
    }
}

// ---------------------------------------------------------------------------
// Kernel 2/4: fp32 GEMM with packed fma.rn.f32x2, double-buffered pipeline.
// EXACT R10/R12 version (measured 203us). Do not touch.
// ---------------------------------------------------------------------------
template <bool SCATTER>
__global__ void __launch_bounds__(64, 7)
gemm_kernel(const float* __restrict__ A,
            const float* __restrict__ Bw,
            float* __restrict__ Cout) {
    const int N = Cc;           // 1024
    const int K = Cc;           // 1024
    __shared__ float As[2][8][64];    // k-major: As[buf][k][row]
    __shared__ float Bs[2][8][72];    // 16B pad per 128B

    const int tid = threadIdx.x;   // 64
    const int tx = tid & 7;
    const int ty = tid >> 3;
    const int rowBase = blockIdx.y * 64;
    const int colBase = blockIdx.x * 64;

    ull acc[4][8];
    #pragma unroll
    for (int p = 0; p < 4; p++)
        #pragma unroll
        for (int j = 0; j < 8; j++) acc[p][j] = 0ULL;

    const int bRow = tid >> 3;               // k within B tile
    const int bColL = (tid & 7) * 8;
    const int bPos = bColL + ((bColL >> 5) << 2);
    const int rb = tx * 8 + ((tx >> 2) << 2);   // padded read base for B

    const float* aSrc = A + (size_t)(rowBase + tid) * K;
    const float* bSrc = Bw + (size_t)bRow * N + colBase + bColL;

    uint32 bDst0 = (uint32)__cvta_generic_to_shared(&Bs[0][bRow][bPos]);
    uint32 bDst1 = (uint32)__cvta_generic_to_shared(&Bs[1][bRow][bPos]);

    // ---- prologue: fill buffer 0 ----
    {
        float4 a0 = *(const float4*)(aSrc + 0);
        float4 a1 = *(const float4*)(aSrc + 4);
        cpasync16(bDst0, bSrc);
        cpasync16(bDst0 + 16, bSrc + 4);
        cpasync_commit();
        As[0][0][tid] = a0.x; As[0][1][tid] = a0.y;
        As[0][2][tid] = a0.z; As[0][3][tid] = a0.w;
        As[0][4][tid] = a1.x; As[0][5][tid] = a1.y;
        As[0][6][tid] = a1.z; As[0][7][tid] = a1.w;
        cpasync_wait0();
    }
    __syncthreads();

    for (int k0 = 0; k0 < K; k0 += 8) {
        const int cur = (k0 >> 3) & 1;
        const int nxt = cur ^ 1;
        const bool has = (k0 + 8) < K;

        float4 n0, n1;
        if (has) {
            uint32 bDstN = nxt ? bDst1 : bDst0;
            cpasync16(bDstN, bSrc + (size_t)(k0 + 8) * N);
            cpasync16(bDstN + 16, bSrc + (size_t)(k0 + 8) * N + 4);
            cpasync_commit();
            n0 = *(const float4*)(aSrc + k0 + 8);
            n1 = *(const float4*)(aSrc + k0 + 12);
        }

        #pragma unroll
        for (int kk = 0; kk < 8; kk++) {
            ulonglong2 av0 = *(const ulonglong2*)&As[cur][kk][ty * 8 + 0];
            ulonglong2 av1 = *(const ulonglong2*)&As[cur][kk][ty * 8 + 4];
            ull ap[4] = {av0.x, av0.y, av1.x, av1.y};
            float4 bv0 = *(const float4*)&Bs[cur][kk][rb + 0];
            float4 bv1 = *(const float4*)&Bs[cur][kk][rb + 4];
            ull bd[8];
            bd[0] = pack2(bv0.x, bv0.x); bd[1] = pack2(bv0.y, bv0.y);
            bd[2] = pack2(bv0.z, bv0.z); bd[3] = pack2(bv0.w, bv0.w);
            bd[4] = pack2(bv1.x, bv1.x); bd[5] = pack2(bv1.y, bv1.y);
            bd[6] = pack2(bv1.z, bv1.z); bd[7] = pack2(bv1.w, bv1.w);
            #pragma unroll
            for (int p = 0; p < 4; p++)
                #pragma unroll
                for (int j = 0; j < 8; j++)
                    FMA2(acc[p][j], ap[p], bd[j]);
        }

        if (has) {
            As[nxt][0][tid] = n0.x; As[nxt][1][tid] = n0.y;
            As[nxt][2][tid] = n0.z; As[nxt][3][tid] = n0.w;
            As[nxt][4][tid] = n1.x; As[nxt][5][tid] = n1.y;
            As[nxt][6][tid] = n1.z; As[nxt][7][tid] = n1.w;
            cpasync_wait0();
            __syncthreads();
        }
    }

    #pragma unroll
    for (int p = 0; p < 4; p++) {
        int m0 = rowBase + ty * 8 + 2 * p;
        #pragma unroll
        for (int j = 0; j < 8; j++) {
            int n = colBase + tx * 8 + j;
            float lo, hi;
            unpack2(acc[p][j], lo, hi);
            if (SCATTER) {
                int h = n >> 6, d = n & (HD - 1);
                int b0i = m0 >> 11, t0 = m0 & (Tt - 1);
                int b1i = (m0 + 1) >> 11, t1 = (m0 + 1) & (Tt - 1);
                g_v[(((size_t)b0i * Hh + h) * Tt + t0) * HD + d] = lo;
                g_v[(((size_t)b1i * Hh + h) * Tt + t1) * HD + d] = hi;
            } else {
                Cout[(size_t)m0 * N + n] = lo;
                Cout[(size_t)(m0 + 1) * N + n] = hi;
            }
        }
    }
}

// ---------------------------------------------------------------------------
// Kernel 3: causal flash attention, SPLIT-K over key-tile parity, Q=4.
// 128 threads; thread = (query-quad qp, qp+32, qp+64, qp+96) x (16-float
// d-quarter, 16B-interleaved). Per key: 4 LDS.128 feed 32 FMA2 (4 queries
// share every V read -> half the smem crossbar traffic of Q=2).
// Two packed score chains serve all 4 queries. Diagonal tiles use a masked
// variant (p zeroed by SEL); off-diagonal loops are branch-free full-128.
// ---------------------------------------------------------------------------
__global__ void __launch_bounds__(128)
attn_kernel() {
    __shared__ ull   skk[128][3];      // key tile, duplicated pairs
    __shared__ float sv[128][HD];      // value tile 32KB
    __shared__ float red[4];

    const int tid     = threadIdx.x;   // 128
    const int quarter = tid & 3;       // d-quarter owner (16 floats)
    const int qp      = tid >> 2;      // query-quad index: 0..31
    const int bh      = blockIdx.y >> 1;
    const int split   = blockIdx.y & 1;
    const int qt      = gridDim.x - 1 - blockIdx.x;   // heavy tiles first
    const int qi0     = qt * 128 + qp;                 // queries: qi0 + 32*v

    // Load 4 queries, pack pairs (q0,q1) and (q2,q3)
    float qx[4], qy[4], qz[4], qn[4];
    #pragma unroll
    for (int v = 0; v < 4; v++) {
        const float* qpr = g_q3 + ((size_t)bh * Tt + qi0 + 32 * v) * 3;
        qx[v] = qpr[0]; qy[v] = qpr[1]; qz[v] = qpr[2];
        qn[v] = sqrtf(qx[v] * qx[v] + qy[v] * qy[v] + qz[v] * qz[v]);
    }
    const ull qx01 = pack2(qx[0], qx[1]), qx23 = pack2(qx[2], qx[3]);
    const ull qy01 = pack2(qy[0], qy[1]), qy23 = pack2(qy[2], qy[3]);
    const ull qz01 = pack2(qz[0], qz[1]), qz23 = pack2(qz[2], qz[3]);
    const float L2E = 1.4426950408889634f;
    const ull l2e2 = pack2(L2E, L2E);

    float m[4], l[4];
    #pragma unroll
    for (int v = 0; v < 4; v++) { m[v] = -1e30f; l[v] = 0.f; }
    ull acc[4][8];
    #pragma unroll
    for (int v = 0; v < 4; v++)
        #pragma unroll
        for (int j = 0; j < 8; j++) acc[v][j] = 0ULL;

    const int kmaxTile = qt * 128 + 127;
    const float* kb = g_ka + (size_t)bh * Tt * 3;
    const float* vb = g_v  + (size_t)bh * Tt * HD;

    for (int s0 = split * 128; s0 <= kmaxTile; s0 += 256) {
        // Key tile (duplicated pairs) + per-tile max |k|
        {
            const float* kpr = kb + (size_t)(s0 + tid) * 3;
            float k0 = kpr[0], k1 = kpr[1], k2 = kpr[2];
            skk[tid][0] = pack2(k0, k0);
            skk[tid][1] = pack2(k1, k1);
            skk[tid][2] = pack2(k2, k2);
            float nk = sqrtf(k0 * k0 + k1 * k1 + k2 * k2);
            #pragma unroll
            for (int o = 16; o; o >>= 1) nk = fmaxf(nk, __shfl_xor_sync(0xffffffffu, nk, o));
            if ((tid & 31) == 0) red[tid >> 5] = nk;
        }
        // Value tile: 2048 float4 / 128 threads
        {
            const float4* vsrc = (const float4*)(vb + (size_t)s0 * HD);
            float4* vdst = (float4*)&sv[0][0];
            #pragma unroll
            for (int i = 0; i < 16; i++) vdst[tid + i * 128] = vsrc[tid + i * 128];
        }
        __syncthreads();

        const float kmx = fmaxf(fmaxf(red[0], red[1]), fmaxf(red[2], red[3]));
        // Rescale all 4 queries to running tile-bound max (Cauchy-Schwarz)
        #pragma unroll
        for (int v = 0; v < 4; v++) {
            const float mn = fmaxf(m[v], qn[v] * kmx);
            const float c = __expf(m[v] - mn);
            m[v] = mn; l[v] *= c;
            const ull cp = pack2(c, c);
            #pragma unroll
            for (int j = 0; j < 8; j++) MUL2_IP(acc[v][j], cp);
        }
        const ull nm01 = pack2(-m[0] * L2E, -m[1] * L2E);
        const ull nm23 = pack2(-m[2] * L2E, -m[3] * L2E);

        const bool diag = (s0 == qt * 128);
        if (!diag) {
            // Off-diagonal: all 128 keys, batch 2, branch-free.
            for (int s = 0; s < 128; s += 2) {
                ull pp[2][4];
                #pragma unroll
                for (int u = 0; u < 2; u++) {
                    const ull kx = skk[s + u][0], ky = skk[s + u][1], kz = skk[s + u][2];
                    ull sc01, sc23;
                    MUL2_N(sc01, qz01, kz); FMA2(sc01, qy01, ky); FMA2(sc01, qx01, kx);
                    MUL2_N(sc23, qz23, kz); FMA2(sc23, qy23, ky); FMA2(sc23, qx23, kx);
                    ull e01, e23;
                    FMA2_N(e01, sc01, l2e2, nm01);
                    FMA2_N(e23, sc23, l2e2, nm23);
                    float e0, e1, e2, e3;
                    unpack2(e01, e0, e1);
                    unpack2(e23, e2, e3);
                    float p0 = exp2f(e0), p1 = exp2f(e1), p2 = exp2f(e2), p3 = exp2f(e3);
                    l[0] += p0; l[1] += p1; l[2] += p2; l[3] += p3;
                    pp[u][0] = pack2(p0, p0); pp[u][1] = pack2(p1, p1);
                    pp[u][2] = pack2(p2, p2); pp[u][3] = pack2(p3, p3);
                }
                #pragma unroll
                for (int u = 0; u < 2; u++) {
                    const ulonglong2* vr = (const ulonglong2*)sv[s + u];
                    #pragma unroll
                    for (int j = 0; j < 4; j++) {
                        ulonglong2 vv = vr[4 * j + quarter];
                        #pragma unroll
                        for (int v = 0; v < 4; v++) {
                            FMA2(acc[v][2 * j + 0], pp[u][v], vv.x);
                            FMA2(acc[v][2 * j + 1], pp[u][v], vv.y);
                        }
                    }
                }
            }
        } else {
            // Diagonal: masked; loop to send of last query (qp+97), batch 2.
            const int sEnd = (qp + 97 + 1) & ~1;     // even bound <= 128
            for (int s = 0; s < sEnd; s += 2) {
                ull pp[2][4];
                #pragma unroll
                for (int u = 0; u < 2; u++) {
                    const ull kx = skk[s + u][0], ky = skk[s + u][1], kz = skk[s + u][2];
                    ull sc01, sc23;
                    MUL2_N(sc01, qz01, kz); FMA2(sc01, qy01, ky); FMA2(sc01, qx01, kx);
                    MUL2_N(sc23, qz23, kz); FMA2(sc23, qy23, ky); FMA2(sc23, qx23, kx);
                    ull e01, e23;
                    FMA2_N(e01, sc01, l2e2, nm01);
                    FMA2_N(e23, sc23, l2e2, nm23);
                    float e0, e1, e2, e3;
                    unpack2(e01, e0, e1);
                    unpack2(e23, e2, e3);
                    float p0 = exp2f(e0), p1 = exp2f(e1), p2 = exp2f(e2), p3 = exp2f(e3);
                    const int sk_ = s + u;
                    p0 = (sk_ <= qp +  0) ? p0 : 0.f;
                    p1 = (sk_ <= qp + 32) ? p1 : 0.f;
                    p2 = (sk_ <= qp + 64) ? p2 : 0.f;
                    p3 = (sk_ <= qp + 96) ? p3 : 0.f;
                    l[0] += p0; l[1] += p1; l[2] += p2; l[3] += p3;
                    pp[u][0] = pack2(p0, p0); pp[u][1] = pack2(p1, p1);
                    pp[u][2] = pack2(p2, p2); pp[u][3] = pack2(p3, p3);
                }
                #pragma unroll
                for (int u = 0; u < 2; u++) {
                    const ulonglong2* vr = (const ulonglong2*)sv[s + u];
                    #pragma unroll
                    for (int j = 0; j < 4; j++) {
                        ulonglong2 vv = vr[4 * j + quarter];
                        #pragma unroll
                        for (int v = 0; v < 4; v++) {
                            FMA2(acc[v][2 * j + 0], pp[u][v], vv.x);
                            FMA2(acc[v][2 * j + 1], pp[u][v], vv.y);
                        }
                    }
                }
            }
        }
        __syncthreads();
    }

    // Write UNNORMALIZED partials + (m, l) to scratch
    {
        const size_t pbase = ((size_t)split * (Bb * Hh) + bh) * Tt;
        #pragma unroll
        for (int v = 0; v < 4; v++) {
            float4* p4 = (float4*)(g_pacc + (pbase + qi0 + 32 * v) * HD);
            #pragma unroll
            for (int j = 0; j < 4; j++) {
                float4 o;
                unpack2(acc[v][2 * j + 0], o.x, o.y);
                unpack2(acc[v][2 * j + 1], o.z, o.w);
                p4[4 * j + quarter] = o;
            }
            if (quarter == 0) {
                float* ml = g_pml + (pbase + qi0 + 32 * v) * 2;
                ml[0] = m[v]; ml[1] = l[v];
            }
        }
    }
}

// ---------------------------------------------------------------------------
// Kernel 3b: split reduce. Thread = (bh, q, quarter-of-64).
// out = (c0*acc0 + c1*acc1) / (c0*l0 + c1*l1), c_i = exp(m_i - max(m0,m1)).
// ---------------------------------------------------------------------------
__global__ void __launch_bounds__(256)
attn_reduce_kernel() {
    const int gid = blockIdx.x * 256 + threadIdx.x;   // 32*2048*4 total
    const int quarter = gid & 3;
    const int q = (gid >> 2) & (Tt - 1);
    const int bh = gid >> 13;                          // / (2048*4)

    const size_t i0 = ((size_t)bh * Tt + q);
    const size_t i1 = ((size_t)(Bb * Hh) + bh) * Tt + q;
    const float m0 = g_pml[i0 * 2 + 0], l0 = g_pml[i0 * 2 + 1];
    const float m1 = g_pml[i1 * 2 + 0], l1 = g_pml[i1 * 2 + 1];
    const float M = fmaxf(m0, m1);
    const float c0 = __expf(m0 - M);
    const float c1 = __expf(m1 - M);
    const float inv = 1.f / (c0 * l0 + c1 * l1);
    const float w0 = c0 * inv, w1 = c1 * inv;

    const float4* a0 = (const float4*)(g_pacc + i0 * HD + quarter * 16);
    const float4* a1 = (const float4*)(g_pacc + i1 * HD + quarter * 16);
    const int b = bh >> 4, h = bh & 15;
    float4* op = (float4*)(g_ao + ((size_t)(b * Tt + q)) * Cc + h * HD + quarter * 16);
    #pragma unroll
    for (int j = 0; j < 4; j++) {
        float4 v0 = a0[j], v1 = a1[j];
        float4 o;
        o.x = v0.x * w0 + v1.x * w1;
        o.y = v0.y * w0 + v1.y * w1;
        o.z = v0.z * w0 + v1.z * w1;
        o.w = v0.w * w0 + v1.w * w1;
        op[j] = o;
    }
}

// ---------------------------------------------------------------------------
extern "C" void kernel_launch(void* const* d_in, const int* in_sizes, int n_in,
                              void* d_out, int out_size) {
    const float* x     = (const float*)d_in[0];
    const float* wq    = (const float*)d_in[1];
    const float* wk    = (const float*)d_in[2];
    const float* wv    = (const float*)d_in[3];
    const float* wo    = (const float*)d_in[4];
    const float* dirs  = (const float*)d_in[5];
    const float* scale = (const float*)d_in[6];
    float* out = (float*)d_out;

    void *p_ao = nullptr;
    cudaGetSymbolAddress(&p_ao, g_ao);

    // 1. QK projection + key transform
    proj_qk_kernel<<<(Bb * Tt) / 8, 128>>>(x, wq, wk, dirs, scale);

    // 2. V projection GEMM (scatter to (b,h,t,64))
    gemm_kernel<true><<<dim3(Cc / 64, (Bb * Tt) / 64), 64>>>(x, wv, nullptr);

    // 3. Flash attention, split-K by key-tile parity, Q=4 V-reuse
    attn_kernel<<<dim3(Tt / 128, Bb * Hh * 2), 128>>>();
    attn_reduce_kernel<<<(Bb * Hh * Tt * 4) / 256, 256>>>();

    // 4. Output projection GEMM
    gemm_kernel<false><<<dim3(Cc / 64, (Bb * Tt) / 64), 64>>>((const float*)p_ao, wo, out);
}

// round 16
// speedup vs baseline: 1.1892x; 1.0467x over previous
#include <cuda_runtime.h>
#include <cuda_bf16.h>
#include <cstdint>

#define Bb 2
#define Tt 2048
#define Cc 1024
#define Hh 16
#define HD 64

typedef unsigned long long ull;
typedef unsigned int uint32;

// Packed f32x2 helpers (sm_103a): only reachable via PTX *.f32x2.
#define FMA2(d, a, b) \
    asm("fma.rn.f32x2 %0, %1, %2, %0;" : "+l"(d) : "l"(a), "l"(b))
#define MUL2_IP(d, a) \
    asm("mul.rn.f32x2 %0, %1, %0;" : "+l"(d) : "l"(a))
#define FMA2_N(d, a, b, c) \
    asm("fma.rn.f32x2 %0, %1, %2, %3;" : "=l"(d) : "l"(a), "l"(b), "l"(c))
#define MUL2_N(d, a, b) \
    asm("mul.rn.f32x2 %0, %1, %2;" : "=l"(d) : "l"(a), "l"(b))

__device__ __forceinline__ ull pack2(float lo, float hi) {
    ull r;
    asm("mov.b64 %0, {%1, %2};" : "=l"(r) : "f"(lo), "f"(hi));
    return r;
}
__device__ __forceinline__ void unpack2(ull v, float& lo, float& hi) {
    asm("mov.b64 {%0, %1}, %2;" : "=f"(lo), "=f"(hi) : "l"(v));
}
// Guaranteed single-instruction MUFU.EX2 (exp2f without fast-math is a
// multi-instruction accurate sequence — this was silently bloating the
// attention inner loop's issue count).
__device__ __forceinline__ float ex2(float x) {
    float r;
    asm("ex2.approx.ftz.f32 %0, %1;" : "=f"(r) : "f"(x));
    return r;
}
__device__ __forceinline__ void cpasync16(uint32 dst, const void* src) {
    asm volatile("cp.async.cg.shared.global [%0], [%1], 16;" :: "r"(dst), "l"(src) : "memory");
}
__device__ __forceinline__ void cpasync_commit() {
    asm volatile("cp.async.commit_group;" ::: "memory");
}
__device__ __forceinline__ void cpasync_wait0() {
    asm volatile("cp.async.wait_group 0;" ::: "memory");
}

// Scratch (allocation-free rule: __device__ globals)
__device__ float g_q3[(size_t)Bb*Hh*Tt*3];           // (b,h,t,3)
__device__ float g_ka[(size_t)Bb*Hh*Tt*3];           // (b,h,t,3) transformed keys
__device__ float g_v [(size_t)Bb*Hh*Tt*HD];          // (b,h,t,64)
__device__ float g_ao[(size_t)Bb*Tt*Cc];             // (b,t,c) attention output
__device__ float g_pacc[2*(size_t)Bb*Hh*Tt*HD];      // split partial acc (unnormalized)
__device__ float g_pml[2*(size_t)Bb*Hh*Tt*2];        // split partial (m, l)

// ---------------------------------------------------------------------------
// Dummy kernel: occupies launch slot #3 so ncu's fixed capture (launch #4)
// lands on attn_kernel. ~1us cost, no side effects.
// ---------------------------------------------------------------------------
__global__ void dummy_kernel() {}

// ---------------------------------------------------------------------------
// Kernel 1: QK projection + fold (scale*I + d d^T) into K.
// ---------------------------------------------------------------------------
__global__ void proj_qk_kernel(const float* __restrict__ x,
                               const float* __restrict__ wq,
                               const float* __restrict__ wk,
                               const float* __restrict__ dirs,
                               const float* __restrict__ scale_p) {
    __shared__ float xs[8][Cc];
    __shared__ float sk[8][48];
    const int tid = threadIdx.x;                 // 128
    const int rowBase = blockIdx.x * 8;

    {
        const float4* src = (const float4*)(x + (size_t)rowBase * Cc);
        float4* dst = (float4*)&xs[0][0];
        #pragma unroll
        for (int i = tid; i < 8 * Cc / 4; i += 128) dst[i] = src[i];
    }
    __syncthreads();

    if (tid < 96) {
        const int col = tid % 48;
        const float* __restrict__ w = (tid < 48) ? wq : wk;
        float acc[8];
        #pragma unroll
        for (int r = 0; r < 8; r++) acc[r] = 0.f;
        for (int i = 0; i < Cc; i += 4) {
            float w0 = w[(i + 0) * 48 + col];
            float w1 = w[(i + 1) * 48 + col];
            float w2 = w[(i + 2) * 48 + col];
            float w3 = w[(i + 3) * 48 + col];
            #pragma unroll
            for (int r = 0; r < 8; r++) {
                float4 xv = *(const float4*)&xs[r][i];
                acc[r] = fmaf(xv.x, w0, fmaf(xv.y, w1, fmaf(xv.z, w2, fmaf(xv.w, w3, acc[r]))));
            }
        }
        const int h = col / 3, d = col % 3;
        if (tid < 48) {
            #pragma unroll
            for (int r = 0; r < 8; r++) {
                int row = rowBase + r;
                int b = row / Tt, t = row % Tt;
                g_q3[(((size_t)b * Hh + h) * Tt + t) * 3 + d] = acc[r];
            }
        } else {
            #pragma unroll
            for (int r = 0; r < 8; r++) sk[r][col] = acc[r];
        }
    }
    __syncthreads();

    {
        const int r = tid >> 4, h = tid & 15;
        const float d0 = dirs[h * 3 + 0], d1 = dirs[h * 3 + 1], d2 = dirs[h * 3 + 2];
        const float sc = scale_p[0];
        const float k0 = sk[r][3 * h + 0], k1 = sk[r][3 * h + 1], k2 = sk[r][3 * h + 2];
        const float dot = d0 * k0 + d1 * k1 + d2 * k2;
        int row = rowBase + r;
        int b = row / Tt, t = row % Tt;
        size_t base = (((size_t)b * Hh + h) * Tt + t) * 3;
        g_ka[base + 0] = sc * k0 + d0 * dot;
        g_ka[base + 1] = sc * k1 + d1 * dot;
        g_ka[base + 2] = sc * k2 + d2 * dot;
    }
}

// ---------------------------------------------------------------------------
// Kernel 2/4: fp32 GEMM with packed fma.rn.f32x2, double-buffered pipeline.
// EXACT R10/R12 version (measured 203us). Do not touch.
// ---------------------------------------------------------------------------
template <bool SCATTER>
__global__ void __launch_bounds__(64, 7)
gemm_kernel(const float* __restrict__ A,
            const float* __restrict__ Bw,
            float* __restrict__ Cout) {
    const int N = Cc;           // 1024
    const int K = Cc;           // 1024
    __shared__ float As[2][8][64];    // k-major: As[buf][k][row]
    __shared__ float Bs[2][8][72];    // 16B pad per 128B

    const int tid = threadIdx.x;   // 64
    const int tx = tid & 7;
    const int ty = tid >> 3;
    const int rowBase = blockIdx.y * 64;
    const int colBase = blockIdx.x * 64;

    ull acc[4][8];
    #pragma unroll
    for (int p = 0; p < 4; p++)
        #pragma unroll
        for (int j = 0; j < 8; j++) acc[p][j] = 0ULL;

    const int bRow = tid >> 3;               // k within B tile
    const int bColL = (tid & 7) * 8;
    const int bPos = bColL + ((bColL >> 5) << 2);
    const int rb = tx * 8 + ((tx >> 2) << 2);   // padded read base for B

    const float* aSrc = A + (size_t)(rowBase + tid) * K;
    const float* bSrc = Bw + (size_t)bRow * N + colBase + bColL;

    uint32 bDst0 = (uint32)__cvta_generic_to_shared(&Bs[0][bRow][bPos]);
    uint32 bDst1 = (uint32)__cvta_generic_to_shared(&Bs[1][bRow][bPos]);

    // ---- prologue: fill buffer 0 ----
    {
        float4 a0 = *(const float4*)(aSrc + 0);
        float4 a1 = *(const float4*)(aSrc + 4);
        cpasync16(bDst0, bSrc);
        cpasync16(bDst0 + 16, bSrc + 4);
        cpasync_commit();
        As[0][0][tid] = a0.x; As[0][1][tid] = a0.y;
        As[0][2][tid] = a0.z; As[0][3][tid] = a0.w;
        As[0][4][tid] = a1.x; As[0][5][tid] = a1.y;
        As[0][6][tid] = a1.z; As[0][7][tid] = a1.w;
        cpasync_wait0();
    }
    __syncthreads();

    for (int k0 = 0; k0 < K; k0 += 8) {
        const int cur = (k0 >> 3) & 1;
        const int nxt = cur ^ 1;
        const bool has = (k0 + 8) < K;

        float4 n0, n1;
        if (has) {
            uint32 bDstN = nxt ? bDst1 : bDst0;
            cpasync16(bDstN, bSrc + (size_t)(k0 + 8) * N);
            cpasync16(bDstN + 16, bSrc + (size_t)(k0 + 8) * N + 4);
            cpasync_commit();
            n0 = *(const float4*)(aSrc + k0 + 8);
            n1 = *(const float4*)(aSrc + k0 + 12);
        }

        #pragma unroll
        for (int kk = 0; kk < 8; kk++) {
            ulonglong2 av0 = *(const ulonglong2*)&As[cur][kk][ty * 8 + 0];
            ulonglong2 av1 = *(const ulonglong2*)&As[cur][kk][ty * 8 + 4];
            ull ap[4] = {av0.x, av0.y, av1.x, av1.y};
            float4 bv0 = *(const float4*)&Bs[cur][kk][rb + 0];
            float4 bv1 = *(const float4*)&Bs[cur][kk][rb + 4];
            ull bd[8];
            bd[0] = pack2(bv0.x, bv0.x); bd[1] = pack2(bv0.y, bv0.y);
            bd[2] = pack2(bv0.z, bv0.z); bd[3] = pack2(bv0.w, bv0.w);
            bd[4] = pack2(bv1.x, bv1.x); bd[5] = pack2(bv1.y, bv1.y);
            bd[6] = pack2(bv1.z, bv1.z); bd[7] = pack2(bv1.w, bv1.w);
            #pragma unroll
            for (int p = 0; p < 4; p++)
                #pragma unroll
                for (int j = 0; j < 8; j++)
                    FMA2(acc[p][j], ap[p], bd[j]);
        }

        if (has) {
            As[nxt][0][tid] = n0.x; As[nxt][1][tid] = n0.y;
            As[nxt][2][tid] = n0.z; As[nxt][3][tid] = n0.w;
            As[nxt][4][tid] = n1.x; As[nxt][5][tid] = n1.y;
            As[nxt][6][tid] = n1.z; As[nxt][7][tid] = n1.w;
            cpasync_wait0();
            __syncthreads();
        }
    }

    #pragma unroll
    for (int p = 0; p < 4; p++) {
        int m0 = rowBase + ty * 8 + 2 * p;
        #pragma unroll
        for (int j = 0; j < 8; j++) {
            int n = colBase + tx * 8 + j;
            float lo, hi;
            unpack2(acc[p][j], lo, hi);
            if (SCATTER) {
                int h = n >> 6, d = n & (HD - 1);
                int b0i = m0 >> 11, t0 = m0 & (Tt - 1);
                int b1i = (m0 + 1) >> 11, t1 = (m0 + 1) & (Tt - 1);
                g_v[(((size_t)b0i * Hh + h) * Tt + t0) * HD + d] = lo;
                g_v[(((size_t)b1i * Hh + h) * Tt + t1) * HD + d] = hi;
            } else {
                Cout[(size_t)m0 * N + n] = lo;
                Cout[(size_t)(m0 + 1) * N + n] = hi;
            }
        }
    }
}

// ---------------------------------------------------------------------------
// Kernel 3: causal flash attention, SPLIT-K over key-tile parity, Q=4.
// 128 threads; thread = (query-quad qp, qp+32, qp+64, qp+96) x (16-float
// d-quarter). Per key: 4 LDS.128 feed 32 FMA2. All exponentials are raw
// MUFU.EX2 via ex2() (single instruction).
// ---------------------------------------------------------------------------
__global__ void __launch_bounds__(128)
attn_kernel() {
    __shared__ ull   skk[128][3];      // key tile, duplicated pairs
    __shared__ float sv[128][HD];      // value tile 32KB
    __shared__ float red[4];

    const int tid     = threadIdx.x;   // 128
    const int quarter = tid & 3;       // d-quarter owner (16 floats)
    const int qp      = tid >> 2;      // query-quad index: 0..31
    const int bh      = blockIdx.y >> 1;
    const int split   = blockIdx.y & 1;
    const int qt      = gridDim.x - 1 - blockIdx.x;   // heavy tiles first
    const int qi0     = qt * 128 + qp;                 // queries: qi0 + 32*v

    // Load 4 queries, pack pairs (q0,q1) and (q2,q3)
    float qx[4], qy[4], qz[4], qn[4];
    #pragma unroll
    for (int v = 0; v < 4; v++) {
        const float* qpr = g_q3 + ((size_t)bh * Tt + qi0 + 32 * v) * 3;
        qx[v] = qpr[0]; qy[v] = qpr[1]; qz[v] = qpr[2];
        qn[v] = sqrtf(qx[v] * qx[v] + qy[v] * qy[v] + qz[v] * qz[v]);
    }
    const ull qx01 = pack2(qx[0], qx[1]), qx23 = pack2(qx[2], qx[3]);
    const ull qy01 = pack2(qy[0], qy[1]), qy23 = pack2(qy[2], qy[3]);
    const ull qz01 = pack2(qz[0], qz[1]), qz23 = pack2(qz[2], qz[3]);
    const float L2E = 1.4426950408889634f;
    const ull l2e2 = pack2(L2E, L2E);

    float m[4], l[4];
    #pragma unroll
    for (int v = 0; v < 4; v++) { m[v] = -1e30f; l[v] = 0.f; }
    ull acc[4][8];
    #pragma unroll
    for (int v = 0; v < 4; v++)
        #pragma unroll
        for (int j = 0; j < 8; j++) acc[v][j] = 0ULL;

    const int kmaxTile = qt * 128 + 127;
    const float* kb = g_ka + (size_t)bh * Tt * 3;
    const float* vb = g_v  + (size_t)bh * Tt * HD;

    for (int s0 = split * 128; s0 <= kmaxTile; s0 += 256) {
        // Key tile (duplicated pairs) + per-tile max |k|
        {
            const float* kpr = kb + (size_t)(s0 + tid) * 3;
            float k0 = kpr[0], k1 = kpr[1], k2 = kpr[2];
            skk[tid][0] = pack2(k0, k0);
            skk[tid][1] = pack2(k1, k1);
            skk[tid][2] = pack2(k2, k2);
            float nk = sqrtf(k0 * k0 + k1 * k1 + k2 * k2);
            #pragma unroll
            for (int o = 16; o; o >>= 1) nk = fmaxf(nk, __shfl_xor_sync(0xffffffffu, nk, o));
            if ((tid & 31) == 0) red[tid >> 5] = nk;
        }
        // Value tile: 2048 float4 / 128 threads
        {
            const float4* vsrc = (const float4*)(vb + (size_t)s0 * HD);
            float4* vdst = (float4*)&sv[0][0];
            #pragma unroll
            for (int i = 0; i < 16; i++) vdst[tid + i * 128] = vsrc[tid + i * 128];
        }
        __syncthreads();

        const float kmx = fmaxf(fmaxf(red[0], red[1]), fmaxf(red[2], red[3]));
        // Rescale all 4 queries to running tile-bound max (Cauchy-Schwarz)
        #pragma unroll
        for (int v = 0; v < 4; v++) {
            const float mn = fmaxf(m[v], qn[v] * kmx);
            const float c = __expf(m[v] - mn);
            m[v] = mn; l[v] *= c;
            const ull cp = pack2(c, c);
            #pragma unroll
            for (int j = 0; j < 8; j++) MUL2_IP(acc[v][j], cp);
        }
        const ull nm01 = pack2(-m[0] * L2E, -m[1] * L2E);
        const ull nm23 = pack2(-m[2] * L2E, -m[3] * L2E);

        const bool diag = (s0 == qt * 128);
        if (!diag) {
            // Off-diagonal: all 128 keys, batch 2, branch-free.
            for (int s = 0; s < 128; s += 2) {
                ull pp[2][4];
                #pragma unroll
                for (int u = 0; u < 2; u++) {
                    const ull kx = skk[s + u][0], ky = skk[s + u][1], kz = skk[s + u][2];
                    ull sc01, sc23;
                    MUL2_N(sc01, qz01, kz); FMA2(sc01, qy01, ky); FMA2(sc01, qx01, kx);
                    MUL2_N(sc23, qz23, kz); FMA2(sc23, qy23, ky); FMA2(sc23, qx23, kx);
                    ull e01, e23;
                    FMA2_N(e01, sc01, l2e2, nm01);
                    FMA2_N(e23, sc23, l2e2, nm23);
                    float e0, e1, e2, e3;
                    unpack2(e01, e0, e1);
                    unpack2(e23, e2, e3);
                    float p0 = ex2(e0), p1 = ex2(e1), p2 = ex2(e2), p3 = ex2(e3);
                    l[0] += p0; l[1] += p1; l[2] += p2; l[3] += p3;
                    pp[u][0] = pack2(p0, p0); pp[u][1] = pack2(p1, p1);
                    pp[u][2] = pack2(p2, p2); pp[u][3] = pack2(p3, p3);
                }
                #pragma unroll
                for (int u = 0; u < 2; u++) {
                    const ulonglong2* vr = (const ulonglong2*)sv[s + u];
                    #pragma unroll
                    for (int j = 0; j < 4; j++) {
                        ulonglong2 vv = vr[4 * j + quarter];
                        #pragma unroll
                        for (int v = 0; v < 4; v++) {
                            FMA2(acc[v][2 * j + 0], pp[u][v], vv.x);
                            FMA2(acc[v][2 * j + 1], pp[u][v], vv.y);
                        }
                    }
                }
            }
        } else {
            // Diagonal: masked; loop to send of last query (qp+97), batch 2.
            const int sEnd = (qp + 97 + 1) & ~1;     // even bound <= 128
            for (int s = 0; s < sEnd; s += 2) {
                ull pp[2][4];
                #pragma unroll
                for (int u = 0; u < 2; u++) {
                    const ull kx = skk[s + u][0], ky = skk[s + u][1], kz = skk[s + u][2];
                    ull sc01, sc23;
                    MUL2_N(sc01, qz01, kz); FMA2(sc01, qy01, ky); FMA2(sc01, qx01, kx);
                    MUL2_N(sc23, qz23, kz); FMA2(sc23, qy23, ky); FMA2(sc23, qx23, kx);
                    ull e01, e23;
                    FMA2_N(e01, sc01, l2e2, nm01);
                    FMA2_N(e23, sc23, l2e2, nm23);
                    float e0, e1, e2, e3;
                    unpack2(e01, e0, e1);
                    unpack2(e23, e2, e3);
                    float p0 = ex2(e0), p1 = ex2(e1), p2 = ex2(e2), p3 = ex2(e3);
                    const int sk_ = s + u;
                    p0 = (sk_ <= qp +  0) ? p0 : 0.f;
                    p1 = (sk_ <= qp + 32) ? p1 : 0.f;
                    p2 = (sk_ <= qp + 64) ? p2 : 0.f;
                    p3 = (sk_ <= qp + 96) ? p3 : 0.f;
                    l[0] += p0; l[1] += p1; l[2] += p2; l[3] += p3;
                    pp[u][0] = pack2(p0, p0); pp[u][1] = pack2(p1, p1);
                    pp[u][2] = pack2(p2, p2); pp[u][3] = pack2(p3, p3);
                }
                #pragma unroll
                for (int u = 0; u < 2; u++) {
                    const ulonglong2* vr = (const ulonglong2*)sv[s + u];
                    #pragma unroll
                    for (int j = 0; j < 4; j++) {
                        ulonglong2 vv = vr[4 * j + quarter];
                        #pragma unroll
                        for (int v = 0; v < 4; v++) {
                            FMA2(acc[v][2 * j + 0], pp[u][v], vv.x);
                            FMA2(acc[v][2 * j + 1], pp[u][v], vv.y);
                        }
                    }
                }
            }
        }
        __syncthreads();
    }

    // Write UNNORMALIZED partials + (m, l) to scratch
    {
        const size_t pbase = ((size_t)split * (Bb * Hh) + bh) * Tt;
        #pragma unroll
        for (int v = 0; v < 4; v++) {
            float4* p4 = (float4*)(g_pacc + (pbase + qi0 + 32 * v) * HD);
            #pragma unroll
            for (int j = 0; j < 4; j++) {
                float4 o;
                unpack2(acc[v][2 * j + 0], o.x, o.y);
                unpack2(acc[v][2 * j + 1], o.z, o.w);
                p4[4 * j + quarter] = o;
            }
            if (quarter == 0) {
                float* ml = g_pml + (pbase + qi0 + 32 * v) * 2;
                ml[0] = m[v]; ml[1] = l[v];
            }
        }
    }
}

// ---------------------------------------------------------------------------
// Kernel 3b: split reduce. Thread = (bh, q, quarter-of-64).
// out = (c0*acc0 + c1*acc1) / (c0*l0 + c1*l1), c_i = exp(m_i - max(m0,m1)).
// ---------------------------------------------------------------------------
__global__ void __launch_bounds__(256)
attn_reduce_kernel() {
    const int gid = blockIdx.x * 256 + threadIdx.x;   // 32*2048*4 total
    const int quarter = gid & 3;
    const int q = (gid >> 2) & (Tt - 1);
    const int bh = gid >> 13;                          // / (2048*4)

    const size_t i0 = ((size_t)bh * Tt + q);
    const size_t i1 = ((size_t)(Bb * Hh) + bh) * Tt + q;
    const float m0 = g_pml[i0 * 2 + 0], l0 = g_pml[i0 * 2 + 1];
    const float m1 = g_pml[i1 * 2 + 0], l1 = g_pml[i1 * 2 + 1];
    const float M = fmaxf(m0, m1);
    const float c0 = __expf(m0 - M);
    const float c1 = __expf(m1 - M);
    const float inv = 1.f / (c0 * l0 + c1 * l1);
    const float w0 = c0 * inv, w1 = c1 * inv;

    const float4* a0 = (const float4*)(g_pacc + i0 * HD + quarter * 16);
    const float4* a1 = (const float4*)(g_pacc + i1 * HD + quarter * 16);
    const int b = bh >> 4, h = bh & 15;
    float4* op = (float4*)(g_ao + ((size_t)(b * Tt + q)) * Cc + h * HD + quarter * 16);
    #pragma unroll
    for (int j = 0; j < 4; j++) {
        float4 v0 = a0[j], v1 = a1[j];
        float4 o;
        o.x = v0.x * w0 + v1.x * w1;
        o.y = v0.y * w0 + v1.y * w1;
        o.z = v0.z * w0 + v1.z * w1;
        o.w = v0.w * w0 + v1.w * w1;
        op[j] = o;
    }
}

// ---------------------------------------------------------------------------
extern "C" void kernel_launch(void* const* d_in, const int* in_sizes, int n_in,
                              void* d_out, int out_size) {
    const float* x     = (const float*)d_in[0];
    const float* wq    = (const float*)d_in[1];
    const float* wk    = (const float*)d_in[2];
    const float* wv    = (const float*)d_in[3];
    const float* wo    = (const float*)d_in[4];
    const float* dirs  = (const float*)d_in[5];
    const float* scale = (const float*)d_in[6];
    float* out = (float*)d_out;

    void *p_ao = nullptr;
    cudaGetSymbolAddress(&p_ao, g_ao);

    // 1. QK projection + key transform
    proj_qk_kernel<<<(Bb * Tt) / 8, 128>>>(x, wq, wk, dirs, scale);

    // 2. V projection GEMM (scatter to (b,h,t,64))
    gemm_kernel<true><<<dim3(Cc / 64, (Bb * Tt) / 64), 64>>>(x, wv, nullptr);

    // 3. Dummy (launch slot #3) so ncu's fixed capture (#4) profiles attn.
    dummy_kernel<<<1, 32>>>();

    // 4. Flash attention, split-K by key-tile parity, Q=4 V-reuse
    attn_kernel<<<dim3(Tt / 128, Bb * Hh * 2), 128>>>();
    attn_reduce_kernel<<<(Bb * Hh * Tt * 4) / 256, 256>>>();

    // 5. Output projection GEMM
    gemm_kernel<false><<<dim3(Cc / 64, (Bb * Tt) / 64), 64>>>((const float*)p_ao, wo, out);
}